// round 10
// baseline (speedup 1.0000x reference)
#include <cuda_runtime.h>
#include <cuda_bf16.h>
#include <math.h>
#include <stdint.h>

#define Bdim   2
#define Tdim   4096
#define Hdim   2048
#define NHdim  16
#define HDdim  128
#define Mdim   8192
#define INTERd 8192
#define KCONV  3
#define EPSf   1e-6f
#define NCHUNK 64
#define CHUNK  64

// GEMM tiling (proven): block 128x128, BK=32 bf16, 2-stage, warp 64x32
#define GBK   32
#define SSTR  40
#define ATILE (128 * SSTR * 2)
#define STAGE (4 * ATILE)
#define DYN_SMEM (2 * STAGE)        // 81920 B -> 2 CTAs/SM

typedef __nv_bfloat16 bf16;

// ---------------- device scratch ----------------
__device__ bf16 g_wcTh[(size_t)Hdim * (KCONV*Hdim)];
__device__ bf16 g_wcTl[(size_t)Hdim * (KCONV*Hdim)];
__device__ bf16 g_wqvTh[(size_t)2 * Hdim * Hdim];
__device__ bf16 g_wqvTl[(size_t)2 * Hdim * Hdim];
__device__ bf16 g_woTh[(size_t)Hdim * Hdim];
__device__ bf16 g_woTl[(size_t)Hdim * Hdim];
__device__ bf16 g_w1Th[(size_t)INTERd * Hdim];
__device__ bf16 g_w1Tl[(size_t)INTERd * Hdim];
__device__ bf16 g_w2Th[(size_t)Hdim * INTERd];
__device__ bf16 g_w2Tl[(size_t)Hdim * INTERd];
__device__ bf16 g_normh[(size_t)Mdim * Hdim];
__device__ bf16 g_norml[(size_t)Mdim * Hdim];
__device__ bf16 g_xh[(size_t)Mdim * Hdim];
__device__ bf16 g_xl[(size_t)Mdim * Hdim];
__device__ bf16 g_scanh[(size_t)Mdim * Hdim];
__device__ bf16 g_scanl[(size_t)Mdim * Hdim];
__device__ bf16 g_interh[(size_t)Mdim * INTERd];
__device__ bf16 g_interl[(size_t)Mdim * INTERd];
__device__ float  g_qv[(size_t)Mdim * 2 * Hdim];
__device__ float  g_h2[(size_t)Mdim * Hdim];
__device__ float  g_part[(size_t)2 * Mdim * Hdim];   // split-K partials
__device__ float  g_dt[Mdim * NHdim];
__device__ float  g_p[Bdim * NHdim * Tdim];
__device__ double g_S[Bdim * NHdim * NCHUNK * HDdim];
__device__ double g_carry[Bdim * NHdim * NCHUNK * HDdim];
__device__ float  g_invf[HDdim / 2];

// ---------------- helpers ----------------
__device__ __forceinline__ void cp16(uint32_t dst, const void* src, int sz) {
    asm volatile("cp.async.cg.shared.global [%0], [%1], 16, %2;\n" :: "r"(dst), "l"(src), "r"(sz));
}
__device__ __forceinline__ void ldsm_x4(uint32_t* r, uint32_t addr) {
    asm volatile("ldmatrix.sync.aligned.m8n8.x4.shared.b16 {%0,%1,%2,%3}, [%4];"
                 : "=r"(r[0]), "=r"(r[1]), "=r"(r[2]), "=r"(r[3]) : "r"(addr));
}
__device__ __forceinline__ void mma_bf(float* c, const uint32_t* a, const uint32_t* b) {
    asm volatile("mma.sync.aligned.m16n8k16.row.col.f32.bf16.bf16.f32 "
                 "{%0,%1,%2,%3}, {%4,%5,%6,%7}, {%8,%9}, {%0,%1,%2,%3};"
                 : "+f"(c[0]), "+f"(c[1]), "+f"(c[2]), "+f"(c[3])
                 : "r"(a[0]), "r"(a[1]), "r"(a[2]), "r"(a[3]), "r"(b[0]), "r"(b[1]));
}
__device__ __forceinline__ void bf16_split(float v, bf16& h, bf16& l) {
    h = __float2bfloat16(v);
    l = __float2bfloat16(v - __bfloat162float(h));
}

// ---------------- init / weight prep ----------------
__global__ void init_invf_kernel() {
    int j = threadIdx.x;
    if (j < HDdim / 2) g_invf[j] = (float)exp(-((double)j / 64.0) * log(10000.0));
}
__global__ void pack_convw_split_kernel(const float* __restrict__ conv_w) {
    int inner = blockIdx.x * 256 + threadIdx.x;
    int o = blockIdx.y;
    if (inner >= KCONV * Hdim) return;
    int k = inner >> 11, i = inner & (Hdim - 1);
    float v = conv_w[((size_t)o * Hdim + i) * KCONV + k];
    bf16 h, l; bf16_split(v, h, l);
    size_t oi = (size_t)o * (KCONV * Hdim) + inner;
    g_wcTh[oi] = h; g_wcTl[oi] = l;
}
__global__ void transpose_split_kernel(const float* __restrict__ in, bf16* __restrict__ oh,
                                       bf16* __restrict__ ol, int R, int C) {
    __shared__ float tile[32][33];
    int c0 = blockIdx.x * 32, r0 = blockIdx.y * 32;
    int x = threadIdx.x, y = threadIdx.y;
    #pragma unroll
    for (int j = 0; j < 32; j += 8) tile[y + j][x] = in[(size_t)(r0 + y + j) * C + c0 + x];
    __syncthreads();
    #pragma unroll
    for (int j = 0; j < 32; j += 8) {
        bf16 h, l; bf16_split(tile[x][y + j], h, l);
        size_t oi = (size_t)(c0 + y + j) * R + r0 + x;
        oh[oi] = h; ol[oi] = l;
    }
}

// ---------------- rmsnorm + split ----------------
__global__ void rmsnorm_split_kernel(const float* __restrict__ x, const float* __restrict__ w,
                                     bf16* __restrict__ yh, bf16* __restrict__ yl) {
    int m = blockIdx.x, t = threadIdx.x;
    const float4* xr = reinterpret_cast<const float4*>(x + (size_t)m * Hdim);
    const float4* wr = reinterpret_cast<const float4*>(w);
    float4 v0 = xr[t], v1 = xr[t + 256];
    float ss = v0.x*v0.x + v0.y*v0.y + v0.z*v0.z + v0.w*v0.w
             + v1.x*v1.x + v1.y*v1.y + v1.z*v1.z + v1.w*v1.w;
    __shared__ float red[8];
    #pragma unroll
    for (int o = 16; o; o >>= 1) ss += __shfl_down_sync(0xffffffffu, ss, o);
    if ((t & 31) == 0) red[t >> 5] = ss;
    __syncthreads();
    if (t < 32) {
        float s = (t < 8) ? red[t] : 0.f;
        #pragma unroll
        for (int o = 4; o; o >>= 1) s += __shfl_down_sync(0xffffffffu, s, o);
        if (t == 0) red[0] = s;
    }
    __syncthreads();
    float sc = rsqrtf(red[0] * (1.0f / Hdim) + EPSf);
    float4 w0 = wr[t], w1 = wr[t + 256];
    float o[8] = { v0.x*sc*w0.x, v0.y*sc*w0.y, v0.z*sc*w0.z, v0.w*sc*w0.w,
                   v1.x*sc*w1.x, v1.y*sc*w1.y, v1.z*sc*w1.z, v1.w*sc*w1.w };
    size_t base = (size_t)m * Hdim;
    bf16 hh[8], ll[8];
    #pragma unroll
    for (int i = 0; i < 8; i++) bf16_split(o[i], hh[i], ll[i]);
    *reinterpret_cast<uint2*>(yh + base + t*4)       = *reinterpret_cast<uint2*>(&hh[0]);
    *reinterpret_cast<uint2*>(yh + base + (t+256)*4) = *reinterpret_cast<uint2*>(&hh[4]);
    *reinterpret_cast<uint2*>(yl + base + t*4)       = *reinterpret_cast<uint2*>(&ll[0]);
    *reinterpret_cast<uint2*>(yl + base + (t+256)*4) = *reinterpret_cast<uint2*>(&ll[4]);
}

// =====================================================================
// 3x-bf16 mma.sync GEMM (proven config) with optional split-K=2.
// =====================================================================
template<bool CONV>
__device__ __forceinline__ void load_stage(uint32_t st, int k0,
    const bf16* __restrict__ Ah, const bf16* __restrict__ Al,
    const bf16* __restrict__ Bth, const bf16* __restrict__ Btl,
    int Kd, int m_base, int n_base, int tid) {
    int kidx = 0, irow = 0;
    if (CONV) { kidx = k0 >> 11; irow = k0 & (Hdim - 1); }
    #pragma unroll
    for (int h = 0; h < 2; h++) {
        int idx = tid + h * 256;
        int row = idx >> 2;
        int ch = idx & 3;
        uint32_t so = (uint32_t)(row * (SSTR * 2) + ch * 16);
        if (CONV) {
            int gm = m_base + row, tp = gm & (Tdim - 1);
            int ok = (tp - 2 + kidx) >= 0;
            size_t ao = (size_t)(ok ? gm - 2 + kidx : 0) * Hdim + irow + ch * 8;
            cp16(st + so,         Ah + ao, ok ? 16 : 0);
            cp16(st + ATILE + so, Al + ao, ok ? 16 : 0);
        } else {
            size_t ao = (size_t)(m_base + row) * Kd + k0 + ch * 8;
            cp16(st + so,         Ah + ao, 16);
            cp16(st + ATILE + so, Al + ao, 16);
        }
        size_t bo = (size_t)(n_base + row) * Kd + k0 + ch * 8;
        cp16(st + 2*ATILE + so, Bth + bo, 16);
        cp16(st + 3*ATILE + so, Btl + bo, 16);
    }
}

template<bool CONV, bool BIAS, bool SILU, bool RESID, bool OUTF32, bool OUTSPLIT, bool SPLITK>
__global__ __launch_bounds__(256)
void bmma_gemm(const bf16* __restrict__ Ah, const bf16* __restrict__ Al,
               const bf16* __restrict__ Bth, const bf16* __restrict__ Btl,
               float* __restrict__ Cf, bf16* __restrict__ Ch, bf16* __restrict__ Cl,
               int N, int Kd, const float* __restrict__ bias, const float* __restrict__ resid) {
    extern __shared__ __align__(16) uint8_t dsm[];
    const int tid = threadIdx.x;
    const int warp = tid >> 5, lane = tid & 31;
    const int g = lane >> 2, tg = lane & 3;
    const int wm = (warp >> 2) * 64;
    const int wn = (warp & 3) * 32;
    const int m_base = blockIdx.y * 128, n_base = blockIdx.x * 128;
    const uint32_t base0 = (uint32_t)__cvta_generic_to_shared(dsm);

    const int klen = SPLITK ? (Kd >> 1) : Kd;
    const int kbeg = SPLITK ? (int)blockIdx.z * klen : 0;

    float acc[4][4][4];
    #pragma unroll
    for (int i = 0; i < 4; i++)
        #pragma unroll
        for (int j = 0; j < 4; j++) { acc[i][j][0]=0.f; acc[i][j][1]=0.f; acc[i][j][2]=0.f; acc[i][j][3]=0.f; }

    const uint32_t aRow = (uint32_t)(lane & 15);
    const uint32_t aChB = (uint32_t)((lane >> 4) * 16);
    const uint32_t bRow = (uint32_t)((lane & 7) + (lane >> 4) * 8);
    const uint32_t bChB = (uint32_t)(((lane >> 3) & 1) * 16);

    const int ntk = klen / GBK;
    load_stage<CONV>(base0, kbeg, Ah, Al, Bth, Btl, Kd, m_base, n_base, tid);
    asm volatile("cp.async.commit_group;" ::: "memory");

    for (int it = 0; it < ntk; ++it) {
        if (it + 1 < ntk) {
            load_stage<CONV>(base0 + (uint32_t)((it + 1) & 1) * STAGE, kbeg + (it + 1) * GBK,
                             Ah, Al, Bth, Btl, Kd, m_base, n_base, tid);
            asm volatile("cp.async.commit_group;" ::: "memory");
            asm volatile("cp.async.wait_group 1;" ::: "memory");
        } else {
            asm volatile("cp.async.wait_group 0;" ::: "memory");
        }
        __syncthreads();
        const uint32_t stg = base0 + (uint32_t)(it & 1) * STAGE;

        #pragma unroll
        for (int ks = 0; ks < 2; ks++) {
            const uint32_t kOffB = (uint32_t)(ks * 32);
            uint32_t Bh[4][2], Bl[4][2], Ahf[4][4], Alf[4][4];
            #pragma unroll
            for (int ntp = 0; ntp < 2; ntp++) {
                uint32_t addr = stg + 2*ATILE + (uint32_t)(wn + ntp*16 + bRow) * (SSTR*2) + kOffB + bChB;
                uint32_t tr[4];
                ldsm_x4(tr, addr);
                Bh[ntp*2][0]=tr[0]; Bh[ntp*2][1]=tr[1]; Bh[ntp*2+1][0]=tr[2]; Bh[ntp*2+1][1]=tr[3];
                ldsm_x4(tr, addr + ATILE);
                Bl[ntp*2][0]=tr[0]; Bl[ntp*2][1]=tr[1]; Bl[ntp*2+1][0]=tr[2]; Bl[ntp*2+1][1]=tr[3];
            }
            #pragma unroll
            for (int mt = 0; mt < 4; mt++)
                ldsm_x4(Ahf[mt], stg + (uint32_t)(wm + mt*16 + aRow) * (SSTR*2) + kOffB + aChB);
            #pragma unroll
            for (int mt = 0; mt < 4; mt++)
                #pragma unroll
                for (int nt = 0; nt < 4; nt++)
                    mma_bf(acc[mt][nt], Ahf[mt], Bl[nt]);
            #pragma unroll
            for (int mt = 0; mt < 4; mt++)
                ldsm_x4(Alf[mt], stg + ATILE + (uint32_t)(wm + mt*16 + aRow) * (SSTR*2) + kOffB + aChB);
            #pragma unroll
            for (int mt = 0; mt < 4; mt++)
                #pragma unroll
                for (int nt = 0; nt < 4; nt++)
                    mma_bf(acc[mt][nt], Alf[mt], Bh[nt]);
            #pragma unroll
            for (int mt = 0; mt < 4; mt++)
                #pragma unroll
                for (int nt = 0; nt < 4; nt++)
                    mma_bf(acc[mt][nt], Ahf[mt], Bh[nt]);
        }
        __syncthreads();
    }

    // epilogue
    float* Pf = SPLITK ? (Cf + (size_t)blockIdx.z * ((size_t)Mdim * N)) : Cf;
    #pragma unroll
    for (int mt = 0; mt < 4; mt++) {
        #pragma unroll
        for (int nt = 0; nt < 4; nt++) {
            int col = n_base + wn + nt * 8 + tg * 2;
            #pragma unroll
            for (int half = 0; half < 2; half++) {
                int row = m_base + wm + mt * 16 + g + half * 8;
                float c0 = acc[mt][nt][half * 2 + 0];
                float c1 = acc[mt][nt][half * 2 + 1];
                if (SPLITK) {
                    float2 o; o.x = c0; o.y = c1;
                    *reinterpret_cast<float2*>(Pf + (size_t)row * N + col) = o;
                } else {
                    if (BIAS) { c0 += bias[col]; c1 += bias[col + 1]; }
                    if (SILU) {
                        c0 = c0 / (1.0f + expf(-c0));
                        c1 = c1 / (1.0f + expf(-c1));
                    }
                    if (RESID) {
                        float2 r = *reinterpret_cast<const float2*>(resid + (size_t)row * N + col);
                        c0 += r.x; c1 += r.y;
                    }
                    if (OUTF32) {
                        float2 o; o.x = c0; o.y = c1;
                        *reinterpret_cast<float2*>(Cf + (size_t)row * N + col) = o;
                    }
                    if (OUTSPLIT) {
                        bf16 h0, l0, h1, l1;
                        bf16_split(c0, h0, l0);
                        bf16_split(c1, h1, l1);
                        __nv_bfloat162 hp; hp.x = h0; hp.y = h1;
                        __nv_bfloat162 lp; lp.x = l0; lp.y = l1;
                        *reinterpret_cast<__nv_bfloat162*>(Ch + (size_t)row * N + col) = hp;
                        *reinterpret_cast<__nv_bfloat162*>(Cl + (size_t)row * N + col) = lp;
                    }
                }
            }
        }
    }
}

// ---------------- split-K reduce: out = P0 + P1 (+bias) (+resid) ----------------
template<bool BIAS, bool RESID, bool OUTF32, bool OUTSPLIT>
__global__ void reduce_splitk(const float* __restrict__ P, int N,
                              const float* __restrict__ bias,
                              const float* __restrict__ resid,
                              float* __restrict__ Cf, bf16* __restrict__ Ch, bf16* __restrict__ Cl) {
    size_t i4 = (size_t)blockIdx.x * 256 + threadIdx.x;
    size_t total4 = (size_t)Mdim * N / 4;
    if (i4 >= total4) return;
    size_t i = i4 * 4;
    float4 a = *reinterpret_cast<const float4*>(P + i);
    float4 b = *reinterpret_cast<const float4*>(P + (size_t)Mdim * N + i);
    float v[4] = { a.x + b.x, a.y + b.y, a.z + b.z, a.w + b.w };
    if (BIAS) {
        int col = (int)(i & (size_t)(N - 1));
        float4 bb = *reinterpret_cast<const float4*>(bias + col);
        v[0] += bb.x; v[1] += bb.y; v[2] += bb.z; v[3] += bb.w;
    }
    if (RESID) {
        float4 r = *reinterpret_cast<const float4*>(resid + i);
        v[0] += r.x; v[1] += r.y; v[2] += r.z; v[3] += r.w;
    }
    if (OUTF32) {
        *reinterpret_cast<float4*>(Cf + i) = make_float4(v[0], v[1], v[2], v[3]);
    }
    if (OUTSPLIT) {
        bf16 hh[4], ll[4];
        #pragma unroll
        for (int j = 0; j < 4; j++) bf16_split(v[j], hh[j], ll[j]);
        *reinterpret_cast<uint2*>(Ch + i) = *reinterpret_cast<uint2*>(&hh[0]);
        *reinterpret_cast<uint2*>(Cl + i) = *reinterpret_cast<uint2*>(&ll[0]);
    }
}

// ---------------- dt / scans (rope fused into scan_final) ----------------
__global__ void dt_kernel(const float* __restrict__ w_dt, const float* __restrict__ b_dt,
                          const float* __restrict__ dt_bias) {
    int m = blockIdx.x, nh = threadIdx.x >> 5, lane = threadIdx.x & 31;
    const bf16* hh = g_normh + (size_t)m * Hdim;
    const bf16* hl = g_norml + (size_t)m * Hdim;
    float s = 0.f;
    for (int k = lane; k < Hdim; k += 32)
        s += (__bfloat162float(hh[k]) + __bfloat162float(hl[k])) * w_dt[(size_t)k * NHdim + nh];
    #pragma unroll
    for (int o = 16; o; o >>= 1) s += __shfl_down_sync(0xffffffffu, s, o);
    if (lane == 0) {
        float x = s + b_dt[nh] + dt_bias[nh];
        g_dt[m * NHdim + nh] = fmaxf(x, 0.f) + log1pf(expf(-fabsf(x)));
    }
}
__global__ void p_scan_kernel(const float* __restrict__ A_log) {
    int warp = threadIdx.x >> 5, lane = threadIdx.x & 31;
    int b = warp >> 4, nh = warp & (NHdim - 1);
    float Anh = -expf(A_log[nh]);
    int t0 = lane * (Tdim / 32);
    float prod = 1.f;
    for (int i = 0; i < Tdim / 32; i++)
        prod *= expf(Anh * g_dt[(b * Tdim + t0 + i) * NHdim + nh]);
    float x = prod;
    #pragma unroll
    for (int o = 1; o < 32; o <<= 1) {
        float y = __shfl_up_sync(0xffffffffu, x, o);
        if (lane >= o) x *= y;
    }
    float excl = __shfl_up_sync(0xffffffffu, x, 1);
    if (lane == 0) excl = 1.f;
    float run = excl;
    float* prow = g_p + warp * Tdim;
    for (int i = 0; i < Tdim / 32; i++) {
        int t = t0 + i;
        run *= expf(Anh * g_dt[(b * Tdim + t) * NHdim + nh]);
        prow[t] = run;
    }
}
__global__ void scan_partial_kernel() {
    int blk = blockIdx.x, bnh = blk >> 6, c = blk & (NCHUNK - 1);
    int b = bnh >> 4, nh = bnh & (NHdim - 1), hd = threadIdx.x;
    const float* prow = g_p + bnh * Tdim;
    double s = 0.0;
    int t0 = c * CHUNK;
    for (int i = 0; i < CHUNK; i++) {
        int t = t0 + i, m = b * Tdim + t;
        float beta = g_dt[m * NHdim + nh], pv = prow[t];
        float v = g_qv[(size_t)m * (2*Hdim) + Hdim + nh * HDdim + hd];
        s += (double)((beta * v) / (pv + EPSf));
    }
    g_S[(size_t)blk * HDdim + hd] = s;
}
__global__ void scan_carry_kernel() {
    int bnh = blockIdx.x, hd = threadIdx.x;
    double carry = 0.0;
    for (int c = 0; c < NCHUNK; c++) {
        size_t idx = ((size_t)bnh * NCHUNK + c) * HDdim + hd;
        g_carry[idx] = carry;
        carry += g_S[idx];
    }
}
__global__ void scan_final_kernel(const int* __restrict__ pos_ids) {
    int blk = blockIdx.x, bnh = blk >> 6, c = blk & (NCHUNK - 1);
    int b = bnh >> 4, nh = bnh & (NHdim - 1), hd = threadIdx.x;
    const float* prow = g_p + bnh * Tdim;
    double s = g_carry[(size_t)blk * HDdim + hd];
    const float invf = g_invf[hd & 63];
    const bool even = (hd & 1) == 0;
    int t0 = c * CHUNK;
    for (int i = 0; i < CHUNK; i++) {
        int t = t0 + i, m = b * Tdim + t;
        float beta = g_dt[m * NHdim + nh], pv = prow[t];
        size_t qvbase = (size_t)m * (2*Hdim) + nh * HDdim + hd;
        float v = g_qv[qvbase + Hdim];
        s += (double)((beta * v) / (pv + EPSf));
        float state = (float)((double)pv * s);
        float qv = g_qv[qvbase];
        float qp = __shfl_xor_sync(0xffffffffu, qv, 1);
        float pos = (float)pos_ids[m];
        float ang = pos * invf;
        float ca = cosf(ang), sa = sinf(ang);
        float qr = even ? (qv * ca - qp * sa) : (qv * ca + qp * sa);
        float outv = qr * state;
        bf16 h, l; bf16_split(outv, h, l);
        size_t oi = (size_t)m * Hdim + nh * HDdim + hd;
        g_scanh[oi] = h; g_scanl[oi] = l;
    }
}

// ---------------- launch ----------------
extern "C" void kernel_launch(void* const* d_in, const int* in_sizes, int n_in,
                              void* d_out, int out_size) {
    const float* hidden  = (const float*)d_in[0];
    const int*   pos_ids = (const int*)  d_in[1];
    const float* conv_w  = (const float*)d_in[2];
    const float* conv_b  = (const float*)d_in[3];
    const float* wq      = (const float*)d_in[4];
    const float* wv      = (const float*)d_in[5];
    const float* w_dt    = (const float*)d_in[6];
    const float* b_dt    = (const float*)d_in[7];
    const float* A_log   = (const float*)d_in[8];
    const float* dt_bias = (const float*)d_in[9];
    const float* wo      = (const float*)d_in[10];
    const float* w1      = (const float*)d_in[11];
    const float* w2      = (const float*)d_in[12];
    const float* norm1_w = (const float*)d_in[13];
    const float* norm2_w = (const float*)d_in[14];
    float* out = (float*)d_out;

    bf16 *wcTh,*wcTl,*wqvTh,*wqvTl,*woTh,*woTl,*w1Th,*w1Tl,*w2Th,*w2Tl;
    bf16 *normh,*norml,*xh,*xl,*scanh,*scanl,*interh,*interl;
    float *pqv,*ph2,*ppart;
    cudaGetSymbolAddress((void**)&wcTh, g_wcTh);     cudaGetSymbolAddress((void**)&wcTl, g_wcTl);
    cudaGetSymbolAddress((void**)&wqvTh, g_wqvTh);   cudaGetSymbolAddress((void**)&wqvTl, g_wqvTl);
    cudaGetSymbolAddress((void**)&woTh, g_woTh);     cudaGetSymbolAddress((void**)&woTl, g_woTl);
    cudaGetSymbolAddress((void**)&w1Th, g_w1Th);     cudaGetSymbolAddress((void**)&w1Tl, g_w1Tl);
    cudaGetSymbolAddress((void**)&w2Th, g_w2Th);     cudaGetSymbolAddress((void**)&w2Tl, g_w2Tl);
    cudaGetSymbolAddress((void**)&normh, g_normh);   cudaGetSymbolAddress((void**)&norml, g_norml);
    cudaGetSymbolAddress((void**)&xh, g_xh);         cudaGetSymbolAddress((void**)&xl, g_xl);
    cudaGetSymbolAddress((void**)&scanh, g_scanh);   cudaGetSymbolAddress((void**)&scanl, g_scanl);
    cudaGetSymbolAddress((void**)&interh, g_interh); cudaGetSymbolAddress((void**)&interl, g_interl);
    cudaGetSymbolAddress((void**)&pqv, g_qv);
    cudaGetSymbolAddress((void**)&ph2, g_h2);
    cudaGetSymbolAddress((void**)&ppart, g_part);

    cudaFuncSetAttribute(bmma_gemm<true,false,false,false,false,false,true>,   cudaFuncAttributeMaxDynamicSharedMemorySize, DYN_SMEM);
    cudaFuncSetAttribute(bmma_gemm<false,false,false,false,false,false,true>,  cudaFuncAttributeMaxDynamicSharedMemorySize, DYN_SMEM);
    cudaFuncSetAttribute(bmma_gemm<false,false,false,false,true,false,false>,  cudaFuncAttributeMaxDynamicSharedMemorySize, DYN_SMEM);
    cudaFuncSetAttribute(bmma_gemm<false,false,true,false,false,true,false>,   cudaFuncAttributeMaxDynamicSharedMemorySize, DYN_SMEM);

    const int RED_BLOCKS = (Mdim * Hdim / 4 + 255) / 256;

    // order: idx 3 = conv GEMM (ncu captures our launch index 3)
    init_invf_kernel<<<1, 64>>>();                                       // 0
    pack_convw_split_kernel<<<dim3(24, Hdim), 256>>>(conv_w);            // 1
    rmsnorm_split_kernel<<<Mdim, 256>>>(hidden, norm1_w, normh, norml);  // 2
    bmma_gemm<true,false,false,false,false,false,true>                   // 3 (ncu target)
        <<<dim3(16,64,2), 256, DYN_SMEM>>>(
        normh, norml, wcTh, wcTl, ppart, nullptr, nullptr, Hdim, KCONV*Hdim, nullptr, nullptr);
    reduce_splitk<true,false,false,true><<<RED_BLOCKS, 256>>>(           // 4
        ppart, Hdim, conv_b, nullptr, nullptr, xh, xl);
    transpose_split_kernel<<<dim3(Hdim/32, Hdim/32), dim3(32,8)>>>(wq, wqvTh, wqvTl, Hdim, Hdim);
    transpose_split_kernel<<<dim3(Hdim/32, Hdim/32), dim3(32,8)>>>(
        wv, wqvTh + (size_t)Hdim*Hdim, wqvTl + (size_t)Hdim*Hdim, Hdim, Hdim);
    transpose_split_kernel<<<dim3(Hdim/32, Hdim/32), dim3(32,8)>>>(wo, woTh, woTl, Hdim, Hdim);
    transpose_split_kernel<<<dim3(INTERd/32, Hdim/32), dim3(32,8)>>>(w1, w1Th, w1Tl, Hdim, INTERd);
    transpose_split_kernel<<<dim3(Hdim/32, INTERd/32), dim3(32,8)>>>(w2, w2Th, w2Tl, INTERd, Hdim);

    // merged q|v GEMM: N = 4096 (no split-K; 6.92 waves already)
    bmma_gemm<false,false,false,false,true,false,false><<<dim3(32,64), 256, DYN_SMEM>>>(
        xh, xl, wqvTh, wqvTl, pqv, nullptr, nullptr, 2*Hdim, Hdim, nullptr, nullptr);
    dt_kernel<<<Mdim, NHdim*32>>>(w_dt, b_dt, dt_bias);
    p_scan_kernel<<<1, 1024>>>(A_log);
    scan_partial_kernel<<<Bdim*NHdim*NCHUNK, HDdim>>>();
    scan_carry_kernel<<<Bdim*NHdim, HDdim>>>();
    scan_final_kernel<<<Bdim*NHdim*NCHUNK, HDdim>>>(pos_ids);

    // wo GEMM split-K + reduce(resid=hidden) -> h2
    bmma_gemm<false,false,false,false,false,false,true><<<dim3(16,64,2), 256, DYN_SMEM>>>(
        scanh, scanl, woTh, woTl, ppart, nullptr, nullptr, Hdim, Hdim, nullptr, nullptr);
    reduce_splitk<false,true,true,false><<<RED_BLOCKS, 256>>>(
        ppart, Hdim, nullptr, hidden, ph2, nullptr, nullptr);

    // mlp branch
    rmsnorm_split_kernel<<<Mdim, 256>>>(ph2, norm2_w, normh, norml);
    bmma_gemm<false,false,true,false,false,true,false><<<dim3(64,64), 256, DYN_SMEM>>>(
        normh, norml, w1Th, w1Tl, nullptr, interh, interl, INTERd, Hdim, nullptr, nullptr);
    // w2 GEMM split-K + reduce(resid=h2) -> out
    bmma_gemm<false,false,false,false,false,false,true><<<dim3(16,64,2), 256, DYN_SMEM>>>(
        interh, interl, w2Th, w2Tl, ppart, nullptr, nullptr, Hdim, INTERd, nullptr, nullptr);
    reduce_splitk<false,true,true,false><<<RED_BLOCKS, 256>>>(
        ppart, Hdim, nullptr, ph2, out, nullptr, nullptr);
}

// round 11
// speedup vs baseline: 1.1265x; 1.1265x over previous
#include <cuda_runtime.h>
#include <cuda_bf16.h>
#include <math.h>
#include <stdint.h>

#define Bdim   2
#define Tdim   4096
#define Hdim   2048
#define NHdim  16
#define HDdim  128
#define Mdim   8192
#define INTERd 8192
#define KCONV  3
#define EPSf   1e-6f
#define NCHUNK 64
#define CHUNK  64

// GEMM tiling (proven): block 128x128, BK=32 bf16, 2-stage, warp 64x32
#define GBK   32
#define SSTR  40
#define ATILE (128 * SSTR * 2)
#define STAGE (4 * ATILE)
#define DYN_SMEM (2 * STAGE)        // 81920 B -> 2 CTAs/SM

typedef __nv_bfloat16 bf16;

// ---------------- device scratch ----------------
__device__ bf16 g_wcTh[(size_t)Hdim * (KCONV*Hdim)];
__device__ bf16 g_wcTl[(size_t)Hdim * (KCONV*Hdim)];
__device__ bf16 g_wqvTh[(size_t)2 * Hdim * Hdim];
__device__ bf16 g_wqvTl[(size_t)2 * Hdim * Hdim];
__device__ bf16 g_woTh[(size_t)Hdim * Hdim];
__device__ bf16 g_woTl[(size_t)Hdim * Hdim];
__device__ bf16 g_w1Th[(size_t)INTERd * Hdim];
__device__ bf16 g_w1Tl[(size_t)INTERd * Hdim];
__device__ bf16 g_w2Th[(size_t)Hdim * INTERd];
__device__ bf16 g_w2Tl[(size_t)Hdim * INTERd];
__device__ bf16 g_normh[(size_t)Mdim * Hdim];
__device__ bf16 g_norml[(size_t)Mdim * Hdim];
__device__ bf16 g_xh[(size_t)Mdim * Hdim];
__device__ bf16 g_xl[(size_t)Mdim * Hdim];
__device__ bf16 g_scanh[(size_t)Mdim * Hdim];
__device__ bf16 g_scanl[(size_t)Mdim * Hdim];
__device__ bf16 g_interh[(size_t)Mdim * INTERd];
__device__ bf16 g_interl[(size_t)Mdim * INTERd];
__device__ float  g_qv[(size_t)Mdim * 2 * Hdim];
__device__ float  g_h2[(size_t)Mdim * Hdim];
__device__ float  g_dt[Mdim * NHdim];
__device__ float  g_p[Bdim * NHdim * Tdim];
__device__ double g_S[Bdim * NHdim * NCHUNK * HDdim];
__device__ double g_carry[Bdim * NHdim * NCHUNK * HDdim];
__device__ float  g_invf[HDdim / 2];

// ---------------- helpers ----------------
__device__ __forceinline__ void cp16(uint32_t dst, const void* src, int sz) {
    asm volatile("cp.async.cg.shared.global [%0], [%1], 16, %2;\n" :: "r"(dst), "l"(src), "r"(sz));
}
__device__ __forceinline__ void ldsm_x4(uint32_t* r, uint32_t addr) {
    asm volatile("ldmatrix.sync.aligned.m8n8.x4.shared.b16 {%0,%1,%2,%3}, [%4];"
                 : "=r"(r[0]), "=r"(r[1]), "=r"(r[2]), "=r"(r[3]) : "r"(addr));
}
__device__ __forceinline__ void mma_bf(float* c, const uint32_t* a, const uint32_t* b) {
    asm volatile("mma.sync.aligned.m16n8k16.row.col.f32.bf16.bf16.f32 "
                 "{%0,%1,%2,%3}, {%4,%5,%6,%7}, {%8,%9}, {%0,%1,%2,%3};"
                 : "+f"(c[0]), "+f"(c[1]), "+f"(c[2]), "+f"(c[3])
                 : "r"(a[0]), "r"(a[1]), "r"(a[2]), "r"(a[3]), "r"(b[0]), "r"(b[1]));
}
__device__ __forceinline__ void bf16_split(float v, bf16& h, bf16& l) {
    h = __float2bfloat16(v);
    l = __float2bfloat16(v - __bfloat162float(h));
}

// ---------------- init / weight prep ----------------
__global__ void init_invf_kernel() {
    int j = threadIdx.x;
    if (j < HDdim / 2) g_invf[j] = (float)exp(-((double)j / 64.0) * log(10000.0));
}
__global__ void pack_convw_split_kernel(const float* __restrict__ conv_w) {
    int inner = blockIdx.x * 256 + threadIdx.x;
    int o = blockIdx.y;
    if (inner >= KCONV * Hdim) return;
    int k = inner >> 11, i = inner & (Hdim - 1);
    float v = conv_w[((size_t)o * Hdim + i) * KCONV + k];
    bf16 h, l; bf16_split(v, h, l);
    size_t oi = (size_t)o * (KCONV * Hdim) + inner;
    g_wcTh[oi] = h; g_wcTl[oi] = l;
}
__global__ void transpose_split_kernel(const float* __restrict__ in, bf16* __restrict__ oh,
                                       bf16* __restrict__ ol, int R, int C) {
    __shared__ float tile[32][33];
    int c0 = blockIdx.x * 32, r0 = blockIdx.y * 32;
    int x = threadIdx.x, y = threadIdx.y;
    #pragma unroll
    for (int j = 0; j < 32; j += 8) tile[y + j][x] = in[(size_t)(r0 + y + j) * C + c0 + x];
    __syncthreads();
    #pragma unroll
    for (int j = 0; j < 32; j += 8) {
        bf16 h, l; bf16_split(tile[x][y + j], h, l);
        size_t oi = (size_t)(c0 + y + j) * R + r0 + x;
        oh[oi] = h; ol[oi] = l;
    }
}

// ---------------- rmsnorm + split ----------------
__global__ void rmsnorm_split_kernel(const float* __restrict__ x, const float* __restrict__ w,
                                     bf16* __restrict__ yh, bf16* __restrict__ yl) {
    int m = blockIdx.x, t = threadIdx.x;
    const float4* xr = reinterpret_cast<const float4*>(x + (size_t)m * Hdim);
    const float4* wr = reinterpret_cast<const float4*>(w);
    float4 v0 = xr[t], v1 = xr[t + 256];
    float ss = v0.x*v0.x + v0.y*v0.y + v0.z*v0.z + v0.w*v0.w
             + v1.x*v1.x + v1.y*v1.y + v1.z*v1.z + v1.w*v1.w;
    __shared__ float red[8];
    #pragma unroll
    for (int o = 16; o; o >>= 1) ss += __shfl_down_sync(0xffffffffu, ss, o);
    if ((t & 31) == 0) red[t >> 5] = ss;
    __syncthreads();
    if (t < 32) {
        float s = (t < 8) ? red[t] : 0.f;
        #pragma unroll
        for (int o = 4; o; o >>= 1) s += __shfl_down_sync(0xffffffffu, s, o);
        if (t == 0) red[0] = s;
    }
    __syncthreads();
    float sc = rsqrtf(red[0] * (1.0f / Hdim) + EPSf);
    float4 w0 = wr[t], w1 = wr[t + 256];
    float o[8] = { v0.x*sc*w0.x, v0.y*sc*w0.y, v0.z*sc*w0.z, v0.w*sc*w0.w,
                   v1.x*sc*w1.x, v1.y*sc*w1.y, v1.z*sc*w1.z, v1.w*sc*w1.w };
    size_t base = (size_t)m * Hdim;
    bf16 hh[8], ll[8];
    #pragma unroll
    for (int i = 0; i < 8; i++) bf16_split(o[i], hh[i], ll[i]);
    *reinterpret_cast<uint2*>(yh + base + t*4)       = *reinterpret_cast<uint2*>(&hh[0]);
    *reinterpret_cast<uint2*>(yh + base + (t+256)*4) = *reinterpret_cast<uint2*>(&hh[4]);
    *reinterpret_cast<uint2*>(yl + base + t*4)       = *reinterpret_cast<uint2*>(&ll[0]);
    *reinterpret_cast<uint2*>(yl + base + (t+256)*4) = *reinterpret_cast<uint2*>(&ll[4]);
}

// =====================================================================
// 3x-bf16 mma.sync GEMM (proven config), loads issued mid-iteration.
// =====================================================================
template<bool CONV>
__device__ __forceinline__ void load_stage(uint32_t st, int k0,
    const bf16* __restrict__ Ah, const bf16* __restrict__ Al,
    const bf16* __restrict__ Bth, const bf16* __restrict__ Btl,
    int Kd, int m_base, int n_base, int tid) {
    int kidx = 0, irow = 0;
    if (CONV) { kidx = k0 >> 11; irow = k0 & (Hdim - 1); }
    #pragma unroll
    for (int h = 0; h < 2; h++) {
        int idx = tid + h * 256;
        int row = idx >> 2;
        int ch = idx & 3;
        uint32_t so = (uint32_t)(row * (SSTR * 2) + ch * 16);
        if (CONV) {
            int gm = m_base + row, tp = gm & (Tdim - 1);
            int ok = (tp - 2 + kidx) >= 0;
            size_t ao = (size_t)(ok ? gm - 2 + kidx : 0) * Hdim + irow + ch * 8;
            cp16(st + so,         Ah + ao, ok ? 16 : 0);
            cp16(st + ATILE + so, Al + ao, ok ? 16 : 0);
        } else {
            size_t ao = (size_t)(m_base + row) * Kd + k0 + ch * 8;
            cp16(st + so,         Ah + ao, 16);
            cp16(st + ATILE + so, Al + ao, 16);
        }
        size_t bo = (size_t)(n_base + row) * Kd + k0 + ch * 8;
        cp16(st + 2*ATILE + so, Bth + bo, 16);
        cp16(st + 3*ATILE + so, Btl + bo, 16);
    }
}

template<bool CONV, bool BIAS, bool SILU, bool RESID, bool OUTF32, bool OUTSPLIT>
__global__ __launch_bounds__(256)
void bmma_gemm(const bf16* __restrict__ Ah, const bf16* __restrict__ Al,
               const bf16* __restrict__ Bth, const bf16* __restrict__ Btl,
               float* __restrict__ Cf, bf16* __restrict__ Ch, bf16* __restrict__ Cl,
               int N, int Kd, const float* __restrict__ bias, const float* __restrict__ resid) {
    extern __shared__ __align__(16) uint8_t dsm[];
    const int tid = threadIdx.x;
    const int warp = tid >> 5, lane = tid & 31;
    const int g = lane >> 2, tg = lane & 3;
    const int wm = (warp >> 2) * 64;
    const int wn = (warp & 3) * 32;
    const int m_base = blockIdx.y * 128, n_base = blockIdx.x * 128;
    const uint32_t base0 = (uint32_t)__cvta_generic_to_shared(dsm);

    float acc[4][4][4];
    #pragma unroll
    for (int i = 0; i < 4; i++)
        #pragma unroll
        for (int j = 0; j < 4; j++) { acc[i][j][0]=0.f; acc[i][j][1]=0.f; acc[i][j][2]=0.f; acc[i][j][3]=0.f; }

    const uint32_t aRow = (uint32_t)(lane & 15);
    const uint32_t aChB = (uint32_t)((lane >> 4) * 16);
    const uint32_t bRow = (uint32_t)((lane & 7) + (lane >> 4) * 8);
    const uint32_t bChB = (uint32_t)(((lane >> 3) & 1) * 16);

    const int ntk = Kd / GBK;
    load_stage<CONV>(base0, 0, Ah, Al, Bth, Btl, Kd, m_base, n_base, tid);
    asm volatile("cp.async.commit_group;" ::: "memory");

    for (int it = 0; it < ntk; ++it) {
        asm volatile("cp.async.wait_group 0;" ::: "memory");
        __syncthreads();
        const uint32_t stg = base0 + (uint32_t)(it & 1) * STAGE;

        #pragma unroll
        for (int ks = 0; ks < 2; ks++) {
            const uint32_t kOffB = (uint32_t)(ks * 32);
            uint32_t Bh[4][2], Bl[4][2], Ahf[4][4], Alf[4][4];
            #pragma unroll
            for (int ntp = 0; ntp < 2; ntp++) {
                uint32_t addr = stg + 2*ATILE + (uint32_t)(wn + ntp*16 + bRow) * (SSTR*2) + kOffB + bChB;
                uint32_t tr[4];
                ldsm_x4(tr, addr);
                Bh[ntp*2][0]=tr[0]; Bh[ntp*2][1]=tr[1]; Bh[ntp*2+1][0]=tr[2]; Bh[ntp*2+1][1]=tr[3];
                ldsm_x4(tr, addr + ATILE);
                Bl[ntp*2][0]=tr[0]; Bl[ntp*2][1]=tr[1]; Bl[ntp*2+1][0]=tr[2]; Bl[ntp*2+1][1]=tr[3];
            }
            #pragma unroll
            for (int mt = 0; mt < 4; mt++)
                ldsm_x4(Ahf[mt], stg + (uint32_t)(wm + mt*16 + aRow) * (SSTR*2) + kOffB + aChB);
            // pass 1: Ah x Bl
            #pragma unroll
            for (int mt = 0; mt < 4; mt++)
                #pragma unroll
                for (int nt = 0; nt < 4; nt++)
                    mma_bf(acc[mt][nt], Ahf[mt], Bl[nt]);
            // issue next-stage loads mid-iteration (ks==0 only), off the ldsm critical path
            if (ks == 0 && it + 1 < ntk) {
                load_stage<CONV>(base0 + (uint32_t)((it + 1) & 1) * STAGE, (it + 1) * GBK,
                                 Ah, Al, Bth, Btl, Kd, m_base, n_base, tid);
                asm volatile("cp.async.commit_group;" ::: "memory");
            }
            #pragma unroll
            for (int mt = 0; mt < 4; mt++)
                ldsm_x4(Alf[mt], stg + ATILE + (uint32_t)(wm + mt*16 + aRow) * (SSTR*2) + kOffB + aChB);
            // pass 2: Al x Bh
            #pragma unroll
            for (int mt = 0; mt < 4; mt++)
                #pragma unroll
                for (int nt = 0; nt < 4; nt++)
                    mma_bf(acc[mt][nt], Alf[mt], Bh[nt]);
            // pass 3: Ah x Bh
            #pragma unroll
            for (int mt = 0; mt < 4; mt++)
                #pragma unroll
                for (int nt = 0; nt < 4; nt++)
                    mma_bf(acc[mt][nt], Ahf[mt], Bh[nt]);
        }
    }

    // epilogue
    #pragma unroll
    for (int mt = 0; mt < 4; mt++) {
        #pragma unroll
        for (int nt = 0; nt < 4; nt++) {
            int col = n_base + wn + nt * 8 + tg * 2;
            #pragma unroll
            for (int half = 0; half < 2; half++) {
                int row = m_base + wm + mt * 16 + g + half * 8;
                float c0 = acc[mt][nt][half * 2 + 0];
                float c1 = acc[mt][nt][half * 2 + 1];
                if (BIAS) { c0 += bias[col]; c1 += bias[col + 1]; }
                if (SILU) {
                    c0 = c0 / (1.0f + expf(-c0));
                    c1 = c1 / (1.0f + expf(-c1));
                }
                if (RESID) {
                    float2 r = *reinterpret_cast<const float2*>(resid + (size_t)row * N + col);
                    c0 += r.x; c1 += r.y;
                }
                if (OUTF32) {
                    float2 o; o.x = c0; o.y = c1;
                    *reinterpret_cast<float2*>(Cf + (size_t)row * N + col) = o;
                }
                if (OUTSPLIT) {
                    bf16 h0, l0, h1, l1;
                    bf16_split(c0, h0, l0);
                    bf16_split(c1, h1, l1);
                    __nv_bfloat162 hp; hp.x = h0; hp.y = h1;
                    __nv_bfloat162 lp; lp.x = l0; lp.y = l1;
                    *reinterpret_cast<__nv_bfloat162*>(Ch + (size_t)row * N + col) = hp;
                    *reinterpret_cast<__nv_bfloat162*>(Cl + (size_t)row * N + col) = lp;
                }
            }
        }
    }
}

// ---------------- dt / scans (rope fused into scan_final) ----------------
__global__ void dt_kernel(const float* __restrict__ w_dt, const float* __restrict__ b_dt,
                          const float* __restrict__ dt_bias) {
    int m = blockIdx.x, nh = threadIdx.x >> 5, lane = threadIdx.x & 31;
    const bf16* hh = g_normh + (size_t)m * Hdim;
    const bf16* hl = g_norml + (size_t)m * Hdim;
    float s = 0.f;
    for (int k = lane; k < Hdim; k += 32)
        s += (__bfloat162float(hh[k]) + __bfloat162float(hl[k])) * w_dt[(size_t)k * NHdim + nh];
    #pragma unroll
    for (int o = 16; o; o >>= 1) s += __shfl_down_sync(0xffffffffu, s, o);
    if (lane == 0) {
        float x = s + b_dt[nh] + dt_bias[nh];
        g_dt[m * NHdim + nh] = fmaxf(x, 0.f) + log1pf(expf(-fabsf(x)));
    }
}
__global__ void p_scan_kernel(const float* __restrict__ A_log) {
    int warp = threadIdx.x >> 5, lane = threadIdx.x & 31;
    int b = warp >> 4, nh = warp & (NHdim - 1);
    float Anh = -expf(A_log[nh]);
    int t0 = lane * (Tdim / 32);
    float prod = 1.f;
    for (int i = 0; i < Tdim / 32; i++)
        prod *= expf(Anh * g_dt[(b * Tdim + t0 + i) * NHdim + nh]);
    float x = prod;
    #pragma unroll
    for (int o = 1; o < 32; o <<= 1) {
        float y = __shfl_up_sync(0xffffffffu, x, o);
        if (lane >= o) x *= y;
    }
    float excl = __shfl_up_sync(0xffffffffu, x, 1);
    if (lane == 0) excl = 1.f;
    float run = excl;
    float* prow = g_p + warp * Tdim;
    for (int i = 0; i < Tdim / 32; i++) {
        int t = t0 + i;
        run *= expf(Anh * g_dt[(b * Tdim + t) * NHdim + nh]);
        prow[t] = run;
    }
}
__global__ void scan_partial_kernel() {
    int blk = blockIdx.x, bnh = blk >> 6, c = blk & (NCHUNK - 1);
    int b = bnh >> 4, nh = bnh & (NHdim - 1), hd = threadIdx.x;
    const float* prow = g_p + bnh * Tdim;
    double s = 0.0;
    int t0 = c * CHUNK;
    for (int i = 0; i < CHUNK; i++) {
        int t = t0 + i, m = b * Tdim + t;
        float beta = g_dt[m * NHdim + nh], pv = prow[t];
        float v = g_qv[(size_t)m * (2*Hdim) + Hdim + nh * HDdim + hd];
        s += (double)((beta * v) / (pv + EPSf));
    }
    g_S[(size_t)blk * HDdim + hd] = s;
}
__global__ void scan_carry_kernel() {
    int bnh = blockIdx.x, hd = threadIdx.x;
    double carry = 0.0;
    for (int c = 0; c < NCHUNK; c++) {
        size_t idx = ((size_t)bnh * NCHUNK + c) * HDdim + hd;
        g_carry[idx] = carry;
        carry += g_S[idx];
    }
}
__global__ void scan_final_kernel(const int* __restrict__ pos_ids) {
    int blk = blockIdx.x, bnh = blk >> 6, c = blk & (NCHUNK - 1);
    int b = bnh >> 4, nh = bnh & (NHdim - 1), hd = threadIdx.x;
    const float* prow = g_p + bnh * Tdim;
    double s = g_carry[(size_t)blk * HDdim + hd];
    const float invf = g_invf[hd & 63];
    const bool even = (hd & 1) == 0;
    int t0 = c * CHUNK;
    for (int i = 0; i < CHUNK; i++) {
        int t = t0 + i, m = b * Tdim + t;
        float beta = g_dt[m * NHdim + nh], pv = prow[t];
        size_t qvbase = (size_t)m * (2*Hdim) + nh * HDdim + hd;
        float v = g_qv[qvbase + Hdim];
        s += (double)((beta * v) / (pv + EPSf));
        float state = (float)((double)pv * s);
        float qv = g_qv[qvbase];
        float qp = __shfl_xor_sync(0xffffffffu, qv, 1);
        float pos = (float)pos_ids[m];
        float ang = pos * invf;
        float ca = cosf(ang), sa = sinf(ang);
        float qr = even ? (qv * ca - qp * sa) : (qv * ca + qp * sa);
        float outv = qr * state;
        bf16 h, l; bf16_split(outv, h, l);
        size_t oi = (size_t)m * Hdim + nh * HDdim + hd;
        g_scanh[oi] = h; g_scanl[oi] = l;
    }
}

// ---------------- launch ----------------
extern "C" void kernel_launch(void* const* d_in, const int* in_sizes, int n_in,
                              void* d_out, int out_size) {
    const float* hidden  = (const float*)d_in[0];
    const int*   pos_ids = (const int*)  d_in[1];
    const float* conv_w  = (const float*)d_in[2];
    const float* conv_b  = (const float*)d_in[3];
    const float* wq      = (const float*)d_in[4];
    const float* wv      = (const float*)d_in[5];
    const float* w_dt    = (const float*)d_in[6];
    const float* b_dt    = (const float*)d_in[7];
    const float* A_log   = (const float*)d_in[8];
    const float* dt_bias = (const float*)d_in[9];
    const float* wo      = (const float*)d_in[10];
    const float* w1      = (const float*)d_in[11];
    const float* w2      = (const float*)d_in[12];
    const float* norm1_w = (const float*)d_in[13];
    const float* norm2_w = (const float*)d_in[14];
    float* out = (float*)d_out;

    bf16 *wcTh,*wcTl,*wqvTh,*wqvTl,*woTh,*woTl,*w1Th,*w1Tl,*w2Th,*w2Tl;
    bf16 *normh,*norml,*xh,*xl,*scanh,*scanl,*interh,*interl;
    float *pqv,*ph2;
    cudaGetSymbolAddress((void**)&wcTh, g_wcTh);     cudaGetSymbolAddress((void**)&wcTl, g_wcTl);
    cudaGetSymbolAddress((void**)&wqvTh, g_wqvTh);   cudaGetSymbolAddress((void**)&wqvTl, g_wqvTl);
    cudaGetSymbolAddress((void**)&woTh, g_woTh);     cudaGetSymbolAddress((void**)&woTl, g_woTl);
    cudaGetSymbolAddress((void**)&w1Th, g_w1Th);     cudaGetSymbolAddress((void**)&w1Tl, g_w1Tl);
    cudaGetSymbolAddress((void**)&w2Th, g_w2Th);     cudaGetSymbolAddress((void**)&w2Tl, g_w2Tl);
    cudaGetSymbolAddress((void**)&normh, g_normh);   cudaGetSymbolAddress((void**)&norml, g_norml);
    cudaGetSymbolAddress((void**)&xh, g_xh);         cudaGetSymbolAddress((void**)&xl, g_xl);
    cudaGetSymbolAddress((void**)&scanh, g_scanh);   cudaGetSymbolAddress((void**)&scanl, g_scanl);
    cudaGetSymbolAddress((void**)&interh, g_interh); cudaGetSymbolAddress((void**)&interl, g_interl);
    cudaGetSymbolAddress((void**)&pqv, g_qv);
    cudaGetSymbolAddress((void**)&ph2, g_h2);

    cudaFuncSetAttribute(bmma_gemm<true,true,false,false,false,true>,   cudaFuncAttributeMaxDynamicSharedMemorySize, DYN_SMEM);
    cudaFuncSetAttribute(bmma_gemm<false,false,false,false,true,false>, cudaFuncAttributeMaxDynamicSharedMemorySize, DYN_SMEM);
    cudaFuncSetAttribute(bmma_gemm<false,false,false,true,true,false>,  cudaFuncAttributeMaxDynamicSharedMemorySize, DYN_SMEM);
    cudaFuncSetAttribute(bmma_gemm<false,false,true,false,false,true>,  cudaFuncAttributeMaxDynamicSharedMemorySize, DYN_SMEM);

    // order: idx 3 = conv GEMM (ncu captures launch index 3)
    init_invf_kernel<<<1, 64>>>();                                       // 0
    pack_convw_split_kernel<<<dim3(24, Hdim), 256>>>(conv_w);            // 1
    rmsnorm_split_kernel<<<Mdim, 256>>>(hidden, norm1_w, normh, norml);  // 2
    bmma_gemm<true,true,false,false,false,true><<<dim3(16,64), 256, DYN_SMEM>>>(   // 3 (ncu)
        normh, norml, wcTh, wcTl, nullptr, xh, xl, Hdim, KCONV*Hdim, conv_b, nullptr);
    transpose_split_kernel<<<dim3(Hdim/32, Hdim/32), dim3(32,8)>>>(wq, wqvTh, wqvTl, Hdim, Hdim);
    transpose_split_kernel<<<dim3(Hdim/32, Hdim/32), dim3(32,8)>>>(
        wv, wqvTh + (size_t)Hdim*Hdim, wqvTl + (size_t)Hdim*Hdim, Hdim, Hdim);
    transpose_split_kernel<<<dim3(Hdim/32, Hdim/32), dim3(32,8)>>>(wo, woTh, woTl, Hdim, Hdim);
    transpose_split_kernel<<<dim3(INTERd/32, Hdim/32), dim3(32,8)>>>(w1, w1Th, w1Tl, Hdim, INTERd);
    transpose_split_kernel<<<dim3(Hdim/32, INTERd/32), dim3(32,8)>>>(w2, w2Th, w2Tl, INTERd, Hdim);

    // merged q|v GEMM: N = 4096
    bmma_gemm<false,false,false,false,true,false><<<dim3(32,64), 256, DYN_SMEM>>>(
        xh, xl, wqvTh, wqvTl, pqv, nullptr, nullptr, 2*Hdim, Hdim, nullptr, nullptr);
    dt_kernel<<<Mdim, NHdim*32>>>(w_dt, b_dt, dt_bias);
    p_scan_kernel<<<1, 1024>>>(A_log);
    scan_partial_kernel<<<Bdim*NHdim*NCHUNK, HDdim>>>();
    scan_carry_kernel<<<Bdim*NHdim, HDdim>>>();
    scan_final_kernel<<<Bdim*NHdim*NCHUNK, HDdim>>>(pos_ids);
    bmma_gemm<false,false,false,true,true,false><<<dim3(16,64), 256, DYN_SMEM>>>(
        scanh, scanl, woTh, woTl, ph2, nullptr, nullptr, Hdim, Hdim, nullptr, hidden);

    // mlp branch
    rmsnorm_split_kernel<<<Mdim, 256>>>(ph2, norm2_w, normh, norml);
    bmma_gemm<false,false,true,false,false,true><<<dim3(64,64), 256, DYN_SMEM>>>(
        normh, norml, w1Th, w1Tl, nullptr, interh, interl, INTERd, Hdim, nullptr, nullptr);
    bmma_gemm<false,false,false,true,true,false><<<dim3(16,64), 256, DYN_SMEM>>>(
        interh, interl, w2Th, w2Tl, out, nullptr, nullptr, Hdim, INTERd, nullptr, ph2);
}

// round 12
// speedup vs baseline: 1.1286x; 1.0019x over previous
#include <cuda_runtime.h>
#include <cuda_bf16.h>
#include <math.h>
#include <stdint.h>

#define Bdim   2
#define Tdim   4096
#define Hdim   2048
#define NHdim  16
#define HDdim  128
#define Mdim   8192
#define INTERd 8192
#define KCONV  3
#define EPSf   1e-6f
#define NCHUNK 64
#define CHUNK  64

// GEMM tiling (proven): block 128x128, BK=32 bf16, 2-stage, warp 64x32
#define GBK   32
#define SSTR  40
#define ATILE (128 * SSTR * 2)
#define STAGE (4 * ATILE)
#define DYN_SMEM (2 * STAGE)        // 81920 B -> 2 CTAs/SM

typedef __nv_bfloat16 bf16;

// ---------------- device scratch ----------------
__device__ bf16 g_wcTh[(size_t)Hdim * (KCONV*Hdim)];
__device__ bf16 g_wcTl[(size_t)Hdim * (KCONV*Hdim)];
__device__ bf16 g_wqvTh[(size_t)2 * Hdim * Hdim];
__device__ bf16 g_wqvTl[(size_t)2 * Hdim * Hdim];
__device__ bf16 g_woTh[(size_t)Hdim * Hdim];
__device__ bf16 g_woTl[(size_t)Hdim * Hdim];
__device__ bf16 g_w1Th[(size_t)INTERd * Hdim];
__device__ bf16 g_w1Tl[(size_t)INTERd * Hdim];
__device__ bf16 g_w2Th[(size_t)Hdim * INTERd];
__device__ bf16 g_w2Tl[(size_t)Hdim * INTERd];
__device__ bf16 g_normh[(size_t)Mdim * Hdim];
__device__ bf16 g_norml[(size_t)Mdim * Hdim];
__device__ bf16 g_xh[(size_t)Mdim * Hdim];
__device__ bf16 g_xl[(size_t)Mdim * Hdim];
__device__ bf16 g_scanh[(size_t)Mdim * Hdim];
__device__ bf16 g_scanl[(size_t)Mdim * Hdim];
__device__ bf16 g_interh[(size_t)Mdim * INTERd];
__device__ bf16 g_interl[(size_t)Mdim * INTERd];
__device__ float  g_qv[(size_t)Mdim * 2 * Hdim];
__device__ float  g_h2[(size_t)Mdim * Hdim];
__device__ float  g_dt[Mdim * NHdim];
__device__ float  g_p[Bdim * NHdim * Tdim];
__device__ double g_S[Bdim * NHdim * NCHUNK * HDdim];
__device__ double g_carry[Bdim * NHdim * NCHUNK * HDdim];
__device__ float  g_invf[HDdim / 2];

// ---------------- helpers ----------------
__device__ __forceinline__ void cp16(uint32_t dst, const void* src, int sz) {
    asm volatile("cp.async.cg.shared.global [%0], [%1], 16, %2;\n" :: "r"(dst), "l"(src), "r"(sz));
}
__device__ __forceinline__ void ldsm_x4(uint32_t* r, uint32_t addr) {
    asm volatile("ldmatrix.sync.aligned.m8n8.x4.shared.b16 {%0,%1,%2,%3}, [%4];"
                 : "=r"(r[0]), "=r"(r[1]), "=r"(r[2]), "=r"(r[3]) : "r"(addr));
}
__device__ __forceinline__ void mma_bf(float* c, const uint32_t* a, const uint32_t* b) {
    asm volatile("mma.sync.aligned.m16n8k16.row.col.f32.bf16.bf16.f32 "
                 "{%0,%1,%2,%3}, {%4,%5,%6,%7}, {%8,%9}, {%0,%1,%2,%3};"
                 : "+f"(c[0]), "+f"(c[1]), "+f"(c[2]), "+f"(c[3])
                 : "r"(a[0]), "r"(a[1]), "r"(a[2]), "r"(a[3]), "r"(b[0]), "r"(b[1]));
}
__device__ __forceinline__ void bf16_split(float v, bf16& h, bf16& l) {
    h = __float2bfloat16(v);
    l = __float2bfloat16(v - __bfloat162float(h));
}

// ---------------- init / weight prep ----------------
__global__ void init_invf_kernel() {
    int j = threadIdx.x;
    if (j < HDdim / 2) g_invf[j] = (float)exp(-((double)j / 64.0) * log(10000.0));
}
__global__ void pack_convw_split_kernel(const float* __restrict__ conv_w) {
    int inner = blockIdx.x * 256 + threadIdx.x;
    int o = blockIdx.y;
    if (inner >= KCONV * Hdim) return;
    int k = inner >> 11, i = inner & (Hdim - 1);
    float v = conv_w[((size_t)o * Hdim + i) * KCONV + k];
    bf16 h, l; bf16_split(v, h, l);
    size_t oi = (size_t)o * (KCONV * Hdim) + inner;
    g_wcTh[oi] = h; g_wcTl[oi] = l;
}
__global__ void transpose_split_kernel(const float* __restrict__ in, bf16* __restrict__ oh,
                                       bf16* __restrict__ ol, int R, int C) {
    __shared__ float tile[32][33];
    int c0 = blockIdx.x * 32, r0 = blockIdx.y * 32;
    int x = threadIdx.x, y = threadIdx.y;
    #pragma unroll
    for (int j = 0; j < 32; j += 8) tile[y + j][x] = in[(size_t)(r0 + y + j) * C + c0 + x];
    __syncthreads();
    #pragma unroll
    for (int j = 0; j < 32; j += 8) {
        bf16 h, l; bf16_split(tile[x][y + j], h, l);
        size_t oi = (size_t)(c0 + y + j) * R + r0 + x;
        oh[oi] = h; ol[oi] = l;
    }
}

// ---------------- rmsnorm + split ----------------
__global__ void rmsnorm_split_kernel(const float* __restrict__ x, const float* __restrict__ w,
                                     bf16* __restrict__ yh, bf16* __restrict__ yl) {
    int m = blockIdx.x, t = threadIdx.x;
    const float4* xr = reinterpret_cast<const float4*>(x + (size_t)m * Hdim);
    const float4* wr = reinterpret_cast<const float4*>(w);
    float4 v0 = xr[t], v1 = xr[t + 256];
    float ss = v0.x*v0.x + v0.y*v0.y + v0.z*v0.z + v0.w*v0.w
             + v1.x*v1.x + v1.y*v1.y + v1.z*v1.z + v1.w*v1.w;
    __shared__ float red[8];
    #pragma unroll
    for (int o = 16; o; o >>= 1) ss += __shfl_down_sync(0xffffffffu, ss, o);
    if ((t & 31) == 0) red[t >> 5] = ss;
    __syncthreads();
    if (t < 32) {
        float s = (t < 8) ? red[t] : 0.f;
        #pragma unroll
        for (int o = 4; o; o >>= 1) s += __shfl_down_sync(0xffffffffu, s, o);
        if (t == 0) red[0] = s;
    }
    __syncthreads();
    float sc = rsqrtf(red[0] * (1.0f / Hdim) + EPSf);
    float4 w0 = wr[t], w1 = wr[t + 256];
    float o[8] = { v0.x*sc*w0.x, v0.y*sc*w0.y, v0.z*sc*w0.z, v0.w*sc*w0.w,
                   v1.x*sc*w1.x, v1.y*sc*w1.y, v1.z*sc*w1.z, v1.w*sc*w1.w };
    size_t base = (size_t)m * Hdim;
    bf16 hh[8], ll[8];
    #pragma unroll
    for (int i = 0; i < 8; i++) bf16_split(o[i], hh[i], ll[i]);
    *reinterpret_cast<uint2*>(yh + base + t*4)       = *reinterpret_cast<uint2*>(&hh[0]);
    *reinterpret_cast<uint2*>(yh + base + (t+256)*4) = *reinterpret_cast<uint2*>(&hh[4]);
    *reinterpret_cast<uint2*>(yl + base + t*4)       = *reinterpret_cast<uint2*>(&ll[0]);
    *reinterpret_cast<uint2*>(yl + base + (t+256)*4) = *reinterpret_cast<uint2*>(&ll[4]);
}

// =====================================================================
// 3x-bf16 mma.sync GEMM: loads split into A/B halves, issued mid-iteration.
// =====================================================================
template<bool CONV>
__device__ __forceinline__ void load_stage_A(uint32_t st, int k0,
    const bf16* __restrict__ Ah, const bf16* __restrict__ Al,
    int Kd, int m_base, int tid) {
    int kidx = 0, irow = 0;
    if (CONV) { kidx = k0 >> 11; irow = k0 & (Hdim - 1); }
    #pragma unroll
    for (int h = 0; h < 2; h++) {
        int idx = tid + h * 256;
        int row = idx >> 2;
        int ch = idx & 3;
        uint32_t so = (uint32_t)(row * (SSTR * 2) + ch * 16);
        if (CONV) {
            int gm = m_base + row, tp = gm & (Tdim - 1);
            int ok = (tp - 2 + kidx) >= 0;
            size_t ao = (size_t)(ok ? gm - 2 + kidx : 0) * Hdim + irow + ch * 8;
            cp16(st + so,         Ah + ao, ok ? 16 : 0);
            cp16(st + ATILE + so, Al + ao, ok ? 16 : 0);
        } else {
            size_t ao = (size_t)(m_base + row) * Kd + k0 + ch * 8;
            cp16(st + so,         Ah + ao, 16);
            cp16(st + ATILE + so, Al + ao, 16);
        }
    }
}
__device__ __forceinline__ void load_stage_B(uint32_t st, int k0,
    const bf16* __restrict__ Bth, const bf16* __restrict__ Btl,
    int Kd, int n_base, int tid) {
    #pragma unroll
    for (int h = 0; h < 2; h++) {
        int idx = tid + h * 256;
        int row = idx >> 2;
        int ch = idx & 3;
        uint32_t so = (uint32_t)(row * (SSTR * 2) + ch * 16);
        size_t bo = (size_t)(n_base + row) * Kd + k0 + ch * 8;
        cp16(st + 2*ATILE + so, Bth + bo, 16);
        cp16(st + 3*ATILE + so, Btl + bo, 16);
    }
}

template<bool CONV, bool BIAS, bool SILU, bool RESID, bool OUTF32, bool OUTSPLIT>
__global__ __launch_bounds__(256)
void bmma_gemm(const bf16* __restrict__ Ah, const bf16* __restrict__ Al,
               const bf16* __restrict__ Bth, const bf16* __restrict__ Btl,
               float* __restrict__ Cf, bf16* __restrict__ Ch, bf16* __restrict__ Cl,
               int N, int Kd, const float* __restrict__ bias, const float* __restrict__ resid) {
    extern __shared__ __align__(16) uint8_t dsm[];
    const int tid = threadIdx.x;
    const int warp = tid >> 5, lane = tid & 31;
    const int g = lane >> 2, tg = lane & 3;
    const int wm = (warp >> 2) * 64;
    const int wn = (warp & 3) * 32;
    const int m_base = blockIdx.y * 128, n_base = blockIdx.x * 128;
    const uint32_t base0 = (uint32_t)__cvta_generic_to_shared(dsm);

    float acc[4][4][4];
    #pragma unroll
    for (int i = 0; i < 4; i++)
        #pragma unroll
        for (int j = 0; j < 4; j++) { acc[i][j][0]=0.f; acc[i][j][1]=0.f; acc[i][j][2]=0.f; acc[i][j][3]=0.f; }

    const uint32_t aRow = (uint32_t)(lane & 15);
    const uint32_t aChB = (uint32_t)((lane >> 4) * 16);
    const uint32_t bRow = (uint32_t)((lane & 7) + (lane >> 4) * 8);
    const uint32_t bChB = (uint32_t)(((lane >> 3) & 1) * 16);

    const int ntk = Kd / GBK;
    load_stage_A<CONV>(base0, 0, Ah, Al, Kd, m_base, tid);
    load_stage_B(base0, 0, Bth, Btl, Kd, n_base, tid);
    asm volatile("cp.async.commit_group;" ::: "memory");

    for (int it = 0; it < ntk; ++it) {
        asm volatile("cp.async.wait_group 0;" ::: "memory");
        __syncthreads();
        const uint32_t stg  = base0 + (uint32_t)(it & 1) * STAGE;
        const uint32_t nstg = base0 + (uint32_t)((it + 1) & 1) * STAGE;
        const bool more = (it + 1 < ntk);

        #pragma unroll
        for (int ks = 0; ks < 2; ks++) {
            const uint32_t kOffB = (uint32_t)(ks * 32);
            uint32_t Bh[4][2], Bl[4][2], Ahf[4][4], Alf[4][4];
            #pragma unroll
            for (int ntp = 0; ntp < 2; ntp++) {
                uint32_t addr = stg + 2*ATILE + (uint32_t)(wn + ntp*16 + bRow) * (SSTR*2) + kOffB + bChB;
                uint32_t tr[4];
                ldsm_x4(tr, addr);
                Bh[ntp*2][0]=tr[0]; Bh[ntp*2][1]=tr[1]; Bh[ntp*2+1][0]=tr[2]; Bh[ntp*2+1][1]=tr[3];
                ldsm_x4(tr, addr + ATILE);
                Bl[ntp*2][0]=tr[0]; Bl[ntp*2][1]=tr[1]; Bl[ntp*2+1][0]=tr[2]; Bl[ntp*2+1][1]=tr[3];
            }
            #pragma unroll
            for (int mt = 0; mt < 4; mt++)
                ldsm_x4(Ahf[mt], stg + (uint32_t)(wm + mt*16 + aRow) * (SSTR*2) + kOffB + aChB);
            // pass 1: Ah x Bl
            #pragma unroll
            for (int mt = 0; mt < 4; mt++)
                #pragma unroll
                for (int nt = 0; nt < 4; nt++)
                    mma_bf(acc[mt][nt], Ahf[mt], Bl[nt]);
            // mid-iteration prefetch, A half after pass 1 (ks==0)
            if (ks == 0 && more)
                load_stage_A<CONV>(nstg, (it + 1) * GBK, Ah, Al, Kd, m_base, tid);
            #pragma unroll
            for (int mt = 0; mt < 4; mt++)
                ldsm_x4(Alf[mt], stg + ATILE + (uint32_t)(wm + mt*16 + aRow) * (SSTR*2) + kOffB + aChB);
            // pass 2: Al x Bh
            #pragma unroll
            for (int mt = 0; mt < 4; mt++)
                #pragma unroll
                for (int nt = 0; nt < 4; nt++)
                    mma_bf(acc[mt][nt], Alf[mt], Bh[nt]);
            // mid-iteration prefetch, B half after pass 2 (ks==0)
            if (ks == 0 && more) {
                load_stage_B(nstg, (it + 1) * GBK, Bth, Btl, Kd, n_base, tid);
                asm volatile("cp.async.commit_group;" ::: "memory");
            }
            // pass 3: Ah x Bh
            #pragma unroll
            for (int mt = 0; mt < 4; mt++)
                #pragma unroll
                for (int nt = 0; nt < 4; nt++)
                    mma_bf(acc[mt][nt], Ahf[mt], Bh[nt]);
        }
    }

    // epilogue
    #pragma unroll
    for (int mt = 0; mt < 4; mt++) {
        #pragma unroll
        for (int nt = 0; nt < 4; nt++) {
            int col = n_base + wn + nt * 8 + tg * 2;
            #pragma unroll
            for (int half = 0; half < 2; half++) {
                int row = m_base + wm + mt * 16 + g + half * 8;
                float c0 = acc[mt][nt][half * 2 + 0];
                float c1 = acc[mt][nt][half * 2 + 1];
                if (BIAS) { c0 += bias[col]; c1 += bias[col + 1]; }
                if (SILU) {
                    c0 = c0 / (1.0f + __expf(-c0));
                    c1 = c1 / (1.0f + __expf(-c1));
                }
                if (RESID) {
                    float2 r = *reinterpret_cast<const float2*>(resid + (size_t)row * N + col);
                    c0 += r.x; c1 += r.y;
                }
                if (OUTF32) {
                    float2 o; o.x = c0; o.y = c1;
                    *reinterpret_cast<float2*>(Cf + (size_t)row * N + col) = o;
                }
                if (OUTSPLIT) {
                    bf16 h0, l0, h1, l1;
                    bf16_split(c0, h0, l0);
                    bf16_split(c1, h1, l1);
                    __nv_bfloat162 hp; hp.x = h0; hp.y = h1;
                    __nv_bfloat162 lp; lp.x = l0; lp.y = l1;
                    *reinterpret_cast<__nv_bfloat162*>(Ch + (size_t)row * N + col) = hp;
                    *reinterpret_cast<__nv_bfloat162*>(Cl + (size_t)row * N + col) = lp;
                }
            }
        }
    }
}

// ---------------- dt / scans (rope fused into scan_final) ----------------
__global__ void dt_kernel(const float* __restrict__ w_dt, const float* __restrict__ b_dt,
                          const float* __restrict__ dt_bias) {
    int m = blockIdx.x, nh = threadIdx.x >> 5, lane = threadIdx.x & 31;
    const bf16* hh = g_normh + (size_t)m * Hdim;
    const bf16* hl = g_norml + (size_t)m * Hdim;
    float s = 0.f;
    for (int k = lane; k < Hdim; k += 32)
        s += (__bfloat162float(hh[k]) + __bfloat162float(hl[k])) * w_dt[(size_t)k * NHdim + nh];
    #pragma unroll
    for (int o = 16; o; o >>= 1) s += __shfl_down_sync(0xffffffffu, s, o);
    if (lane == 0) {
        float x = s + b_dt[nh] + dt_bias[nh];
        g_dt[m * NHdim + nh] = fmaxf(x, 0.f) + log1pf(expf(-fabsf(x)));
    }
}
__global__ void p_scan_kernel(const float* __restrict__ A_log) {
    int warp = threadIdx.x >> 5, lane = threadIdx.x & 31;
    int b = warp >> 4, nh = warp & (NHdim - 1);
    float Anh = -expf(A_log[nh]);
    int t0 = lane * (Tdim / 32);
    float prod = 1.f;
    for (int i = 0; i < Tdim / 32; i++)
        prod *= expf(Anh * g_dt[(b * Tdim + t0 + i) * NHdim + nh]);
    float x = prod;
    #pragma unroll
    for (int o = 1; o < 32; o <<= 1) {
        float y = __shfl_up_sync(0xffffffffu, x, o);
        if (lane >= o) x *= y;
    }
    float excl = __shfl_up_sync(0xffffffffu, x, 1);
    if (lane == 0) excl = 1.f;
    float run = excl;
    float* prow = g_p + warp * Tdim;
    for (int i = 0; i < Tdim / 32; i++) {
        int t = t0 + i;
        run *= expf(Anh * g_dt[(b * Tdim + t) * NHdim + nh]);
        prow[t] = run;
    }
}
__global__ void scan_partial_kernel() {
    int blk = blockIdx.x, bnh = blk >> 6, c = blk & (NCHUNK - 1);
    int b = bnh >> 4, nh = bnh & (NHdim - 1), hd = threadIdx.x;
    const float* prow = g_p + bnh * Tdim;
    double s = 0.0;
    int t0 = c * CHUNK;
    for (int i = 0; i < CHUNK; i++) {
        int t = t0 + i, m = b * Tdim + t;
        float beta = g_dt[m * NHdim + nh], pv = prow[t];
        float v = g_qv[(size_t)m * (2*Hdim) + Hdim + nh * HDdim + hd];
        s += (double)((beta * v) / (pv + EPSf));
    }
    g_S[(size_t)blk * HDdim + hd] = s;
}
__global__ void scan_carry_kernel() {
    int bnh = blockIdx.x, hd = threadIdx.x;
    double carry = 0.0;
    for (int c = 0; c < NCHUNK; c++) {
        size_t idx = ((size_t)bnh * NCHUNK + c) * HDdim + hd;
        g_carry[idx] = carry;
        carry += g_S[idx];
    }
}
__global__ void scan_final_kernel(const int* __restrict__ pos_ids) {
    int blk = blockIdx.x, bnh = blk >> 6, c = blk & (NCHUNK - 1);
    int b = bnh >> 4, nh = bnh & (NHdim - 1), hd = threadIdx.x;
    const float* prow = g_p + bnh * Tdim;
    double s = g_carry[(size_t)blk * HDdim + hd];
    const float invf = g_invf[hd & 63];
    const bool even = (hd & 1) == 0;
    int t0 = c * CHUNK;
    for (int i = 0; i < CHUNK; i++) {
        int t = t0 + i, m = b * Tdim + t;
        float beta = g_dt[m * NHdim + nh], pv = prow[t];
        size_t qvbase = (size_t)m * (2*Hdim) + nh * HDdim + hd;
        float v = g_qv[qvbase + Hdim];
        s += (double)((beta * v) / (pv + EPSf));
        float state = (float)((double)pv * s);
        float qv = g_qv[qvbase];
        float qp = __shfl_xor_sync(0xffffffffu, qv, 1);
        float pos = (float)pos_ids[m];
        float ang = pos * invf;
        float ca = cosf(ang), sa = sinf(ang);
        float qr = even ? (qv * ca - qp * sa) : (qv * ca + qp * sa);
        float outv = qr * state;
        bf16 h, l; bf16_split(outv, h, l);
        size_t oi = (size_t)m * Hdim + nh * HDdim + hd;
        g_scanh[oi] = h; g_scanl[oi] = l;
    }
}

// ---------------- launch ----------------
extern "C" void kernel_launch(void* const* d_in, const int* in_sizes, int n_in,
                              void* d_out, int out_size) {
    const float* hidden  = (const float*)d_in[0];
    const int*   pos_ids = (const int*)  d_in[1];
    const float* conv_w  = (const float*)d_in[2];
    const float* conv_b  = (const float*)d_in[3];
    const float* wq      = (const float*)d_in[4];
    const float* wv      = (const float*)d_in[5];
    const float* w_dt    = (const float*)d_in[6];
    const float* b_dt    = (const float*)d_in[7];
    const float* A_log   = (const float*)d_in[8];
    const float* dt_bias = (const float*)d_in[9];
    const float* wo      = (const float*)d_in[10];
    const float* w1      = (const float*)d_in[11];
    const float* w2      = (const float*)d_in[12];
    const float* norm1_w = (const float*)d_in[13];
    const float* norm2_w = (const float*)d_in[14];
    float* out = (float*)d_out;

    bf16 *wcTh,*wcTl,*wqvTh,*wqvTl,*woTh,*woTl,*w1Th,*w1Tl,*w2Th,*w2Tl;
    bf16 *normh,*norml,*xh,*xl,*scanh,*scanl,*interh,*interl;
    float *pqv,*ph2;
    cudaGetSymbolAddress((void**)&wcTh, g_wcTh);     cudaGetSymbolAddress((void**)&wcTl, g_wcTl);
    cudaGetSymbolAddress((void**)&wqvTh, g_wqvTh);   cudaGetSymbolAddress((void**)&wqvTl, g_wqvTl);
    cudaGetSymbolAddress((void**)&woTh, g_woTh);     cudaGetSymbolAddress((void**)&woTl, g_woTl);
    cudaGetSymbolAddress((void**)&w1Th, g_w1Th);     cudaGetSymbolAddress((void**)&w1Tl, g_w1Tl);
    cudaGetSymbolAddress((void**)&w2Th, g_w2Th);     cudaGetSymbolAddress((void**)&w2Tl, g_w2Tl);
    cudaGetSymbolAddress((void**)&normh, g_normh);   cudaGetSymbolAddress((void**)&norml, g_norml);
    cudaGetSymbolAddress((void**)&xh, g_xh);         cudaGetSymbolAddress((void**)&xl, g_xl);
    cudaGetSymbolAddress((void**)&scanh, g_scanh);   cudaGetSymbolAddress((void**)&scanl, g_scanl);
    cudaGetSymbolAddress((void**)&interh, g_interh); cudaGetSymbolAddress((void**)&interl, g_interl);
    cudaGetSymbolAddress((void**)&pqv, g_qv);
    cudaGetSymbolAddress((void**)&ph2, g_h2);

    cudaFuncSetAttribute(bmma_gemm<true,true,false,false,false,true>,   cudaFuncAttributeMaxDynamicSharedMemorySize, DYN_SMEM);
    cudaFuncSetAttribute(bmma_gemm<false,false,false,false,true,false>, cudaFuncAttributeMaxDynamicSharedMemorySize, DYN_SMEM);
    cudaFuncSetAttribute(bmma_gemm<false,false,false,true,true,false>,  cudaFuncAttributeMaxDynamicSharedMemorySize, DYN_SMEM);
    cudaFuncSetAttribute(bmma_gemm<false,false,true,false,false,true>,  cudaFuncAttributeMaxDynamicSharedMemorySize, DYN_SMEM);

    // order: idx 3 = conv GEMM (ncu captures launch index 3)
    init_invf_kernel<<<1, 64>>>();                                       // 0
    pack_convw_split_kernel<<<dim3(24, Hdim), 256>>>(conv_w);            // 1
    rmsnorm_split_kernel<<<Mdim, 256>>>(hidden, norm1_w, normh, norml);  // 2
    bmma_gemm<true,true,false,false,false,true><<<dim3(16,64), 256, DYN_SMEM>>>(   // 3 (ncu)
        normh, norml, wcTh, wcTl, nullptr, xh, xl, Hdim, KCONV*Hdim, conv_b, nullptr);
    transpose_split_kernel<<<dim3(Hdim/32, Hdim/32), dim3(32,8)>>>(wq, wqvTh, wqvTl, Hdim, Hdim);
    transpose_split_kernel<<<dim3(Hdim/32, Hdim/32), dim3(32,8)>>>(
        wv, wqvTh + (size_t)Hdim*Hdim, wqvTl + (size_t)Hdim*Hdim, Hdim, Hdim);
    transpose_split_kernel<<<dim3(Hdim/32, Hdim/32), dim3(32,8)>>>(wo, woTh, woTl, Hdim, Hdim);
    transpose_split_kernel<<<dim3(INTERd/32, Hdim/32), dim3(32,8)>>>(w1, w1Th, w1Tl, Hdim, INTERd);
    transpose_split_kernel<<<dim3(Hdim/32, INTERd/32), dim3(32,8)>>>(w2, w2Th, w2Tl, INTERd, Hdim);

    // merged q|v GEMM: N = 4096
    bmma_gemm<false,false,false,false,true,false><<<dim3(32,64), 256, DYN_SMEM>>>(
        xh, xl, wqvTh, wqvTl, pqv, nullptr, nullptr, 2*Hdim, Hdim, nullptr, nullptr);
    dt_kernel<<<Mdim, NHdim*32>>>(w_dt, b_dt, dt_bias);
    p_scan_kernel<<<1, 1024>>>(A_log);
    scan_partial_kernel<<<Bdim*NHdim*NCHUNK, HDdim>>>();
    scan_carry_kernel<<<Bdim*NHdim, HDdim>>>();
    scan_final_kernel<<<Bdim*NHdim*NCHUNK, HDdim>>>(pos_ids);
    bmma_gemm<false,false,false,true,true,false><<<dim3(16,64), 256, DYN_SMEM>>>(
        scanh, scanl, woTh, woTl, ph2, nullptr, nullptr, Hdim, Hdim, nullptr, hidden);

    // mlp branch
    rmsnorm_split_kernel<<<Mdim, 256>>>(ph2, norm2_w, normh, norml);
    bmma_gemm<false,false,true,false,false,true><<<dim3(64,64), 256, DYN_SMEM>>>(
        normh, norml, w1Th, w1Tl, nullptr, interh, interl, INTERd, Hdim, nullptr, nullptr);
    bmma_gemm<false,false,false,true,true,false><<<dim3(16,64), 256, DYN_SMEM>>>(
        interh, interl, w2Th, w2Tl, out, nullptr, nullptr, Hdim, INTERd, nullptr, ph2);
}

// round 13
// speedup vs baseline: 1.1429x; 1.0126x over previous
#include <cuda_runtime.h>
#include <cuda_bf16.h>
#include <math.h>
#include <stdint.h>

#define Bdim   2
#define Tdim   4096
#define Hdim   2048
#define NHdim  16
#define HDdim  128
#define Mdim   8192
#define INTERd 8192
#define KCONV  3
#define EPSf   1e-6f
#define NCHUNK 64
#define CHUNK  64

// GEMM tiling (proven): block 128x128, BK=32 bf16, 2-stage, warp 64x32
#define GBK   32
#define SSTR  40
#define ATILE (128 * SSTR * 2)
#define STAGE (4 * ATILE)
#define DYN_SMEM (2 * STAGE)        // 81920 B -> 2 CTAs/SM

typedef __nv_bfloat16 bf16;

// ---------------- device scratch ----------------
__device__ bf16 g_wcTh[(size_t)Hdim * (KCONV*Hdim)];
__device__ bf16 g_wcTl[(size_t)Hdim * (KCONV*Hdim)];
__device__ bf16 g_wqvTh[(size_t)2 * Hdim * Hdim];
__device__ bf16 g_wqvTl[(size_t)2 * Hdim * Hdim];
__device__ bf16 g_woTh[(size_t)Hdim * Hdim];
__device__ bf16 g_woTl[(size_t)Hdim * Hdim];
__device__ bf16 g_w1Th[(size_t)INTERd * Hdim];
__device__ bf16 g_w1Tl[(size_t)INTERd * Hdim];
__device__ bf16 g_w2Th[(size_t)Hdim * INTERd];
__device__ bf16 g_w2Tl[(size_t)Hdim * INTERd];
__device__ bf16 g_normh[(size_t)Mdim * Hdim];
__device__ bf16 g_norml[(size_t)Mdim * Hdim];
__device__ bf16 g_xh[(size_t)Mdim * Hdim];
__device__ bf16 g_xl[(size_t)Mdim * Hdim];
__device__ bf16 g_scanh[(size_t)Mdim * Hdim];
__device__ bf16 g_scanl[(size_t)Mdim * Hdim];
__device__ bf16 g_interh[(size_t)Mdim * INTERd];
__device__ bf16 g_interl[(size_t)Mdim * INTERd];
__device__ float  g_qv[(size_t)Mdim * 2 * Hdim];
__device__ float  g_h2[(size_t)Mdim * Hdim];
__device__ float  g_dt[Mdim * NHdim];
__device__ float  g_p[Bdim * NHdim * Tdim];
__device__ double g_S[Bdim * NHdim * NCHUNK * HDdim];
__device__ double g_carry[Bdim * NHdim * NCHUNK * HDdim];
__device__ float  g_invf[HDdim / 2];

// ---------------- helpers ----------------
__device__ __forceinline__ void cp16(uint32_t dst, const void* src, int sz) {
    asm volatile("cp.async.cg.shared.global [%0], [%1], 16, %2;\n" :: "r"(dst), "l"(src), "r"(sz));
}
__device__ __forceinline__ void ldsm_x4(uint32_t* r, uint32_t addr) {
    asm volatile("ldmatrix.sync.aligned.m8n8.x4.shared.b16 {%0,%1,%2,%3}, [%4];"
                 : "=r"(r[0]), "=r"(r[1]), "=r"(r[2]), "=r"(r[3]) : "r"(addr));
}
__device__ __forceinline__ void mma_bf(float* c, const uint32_t* a, const uint32_t* b) {
    asm volatile("mma.sync.aligned.m16n8k16.row.col.f32.bf16.bf16.f32 "
                 "{%0,%1,%2,%3}, {%4,%5,%6,%7}, {%8,%9}, {%0,%1,%2,%3};"
                 : "+f"(c[0]), "+f"(c[1]), "+f"(c[2]), "+f"(c[3])
                 : "r"(a[0]), "r"(a[1]), "r"(a[2]), "r"(a[3]), "r"(b[0]), "r"(b[1]));
}
__device__ __forceinline__ void bf16_split(float v, bf16& h, bf16& l) {
    h = __float2bfloat16(v);
    l = __float2bfloat16(v - __bfloat162float(h));
}

// ---------------- init / weight prep ----------------
__global__ void init_invf_kernel() {
    int j = threadIdx.x;
    if (j < HDdim / 2) g_invf[j] = (float)exp(-((double)j / 64.0) * log(10000.0));
}
__global__ void pack_convw_split_kernel(const float* __restrict__ conv_w) {
    int inner = blockIdx.x * 256 + threadIdx.x;
    int o = blockIdx.y;
    if (inner >= KCONV * Hdim) return;
    int k = inner >> 11, i = inner & (Hdim - 1);
    float v = conv_w[((size_t)o * Hdim + i) * KCONV + k];
    bf16 h, l; bf16_split(v, h, l);
    size_t oi = (size_t)o * (KCONV * Hdim) + inner;
    g_wcTh[oi] = h; g_wcTl[oi] = l;
}
__global__ void transpose_split_kernel(const float* __restrict__ in, bf16* __restrict__ oh,
                                       bf16* __restrict__ ol, int R, int C) {
    __shared__ float tile[32][33];
    int c0 = blockIdx.x * 32, r0 = blockIdx.y * 32;
    int x = threadIdx.x, y = threadIdx.y;
    #pragma unroll
    for (int j = 0; j < 32; j += 8) tile[y + j][x] = in[(size_t)(r0 + y + j) * C + c0 + x];
    __syncthreads();
    #pragma unroll
    for (int j = 0; j < 32; j += 8) {
        bf16 h, l; bf16_split(tile[x][y + j], h, l);
        size_t oi = (size_t)(c0 + y + j) * R + r0 + x;
        oh[oi] = h; ol[oi] = l;
    }
}

// ---------------- rmsnorm + split ----------------
__global__ void rmsnorm_split_kernel(const float* __restrict__ x, const float* __restrict__ w,
                                     bf16* __restrict__ yh, bf16* __restrict__ yl) {
    int m = blockIdx.x, t = threadIdx.x;
    const float4* xr = reinterpret_cast<const float4*>(x + (size_t)m * Hdim);
    const float4* wr = reinterpret_cast<const float4*>(w);
    float4 v0 = xr[t], v1 = xr[t + 256];
    float ss = v0.x*v0.x + v0.y*v0.y + v0.z*v0.z + v0.w*v0.w
             + v1.x*v1.x + v1.y*v1.y + v1.z*v1.z + v1.w*v1.w;
    __shared__ float red[8];
    #pragma unroll
    for (int o = 16; o; o >>= 1) ss += __shfl_down_sync(0xffffffffu, ss, o);
    if ((t & 31) == 0) red[t >> 5] = ss;
    __syncthreads();
    if (t < 32) {
        float s = (t < 8) ? red[t] : 0.f;
        #pragma unroll
        for (int o = 4; o; o >>= 1) s += __shfl_down_sync(0xffffffffu, s, o);
        if (t == 0) red[0] = s;
    }
    __syncthreads();
    float sc = rsqrtf(red[0] * (1.0f / Hdim) + EPSf);
    float4 w0 = wr[t], w1 = wr[t + 256];
    float o[8] = { v0.x*sc*w0.x, v0.y*sc*w0.y, v0.z*sc*w0.z, v0.w*sc*w0.w,
                   v1.x*sc*w1.x, v1.y*sc*w1.y, v1.z*sc*w1.z, v1.w*sc*w1.w };
    size_t base = (size_t)m * Hdim;
    bf16 hh[8], ll[8];
    #pragma unroll
    for (int i = 0; i < 8; i++) bf16_split(o[i], hh[i], ll[i]);
    *reinterpret_cast<uint2*>(yh + base + t*4)       = *reinterpret_cast<uint2*>(&hh[0]);
    *reinterpret_cast<uint2*>(yh + base + (t+256)*4) = *reinterpret_cast<uint2*>(&hh[4]);
    *reinterpret_cast<uint2*>(yl + base + t*4)       = *reinterpret_cast<uint2*>(&ll[0]);
    *reinterpret_cast<uint2*>(yl + base + (t+256)*4) = *reinterpret_cast<uint2*>(&ll[4]);
}

// =====================================================================
// 3x-bf16 mma.sync GEMM: loads split into A/B halves, issued mid-iteration.
// =====================================================================
template<bool CONV>
__device__ __forceinline__ void load_stage_A(uint32_t st, int k0,
    const bf16* __restrict__ Ah, const bf16* __restrict__ Al,
    int Kd, int m_base, int tid) {
    int kidx = 0, irow = 0;
    if (CONV) { kidx = k0 >> 11; irow = k0 & (Hdim - 1); }
    #pragma unroll
    for (int h = 0; h < 2; h++) {
        int idx = tid + h * 256;
        int row = idx >> 2;
        int ch = idx & 3;
        uint32_t so = (uint32_t)(row * (SSTR * 2) + ch * 16);
        if (CONV) {
            int gm = m_base + row, tp = gm & (Tdim - 1);
            int ok = (tp - 2 + kidx) >= 0;
            size_t ao = (size_t)(ok ? gm - 2 + kidx : 0) * Hdim + irow + ch * 8;
            cp16(st + so,         Ah + ao, ok ? 16 : 0);
            cp16(st + ATILE + so, Al + ao, ok ? 16 : 0);
        } else {
            size_t ao = (size_t)(m_base + row) * Kd + k0 + ch * 8;
            cp16(st + so,         Ah + ao, 16);
            cp16(st + ATILE + so, Al + ao, 16);
        }
    }
}
__device__ __forceinline__ void load_stage_B(uint32_t st, int k0,
    const bf16* __restrict__ Bth, const bf16* __restrict__ Btl,
    int Kd, int n_base, int tid) {
    #pragma unroll
    for (int h = 0; h < 2; h++) {
        int idx = tid + h * 256;
        int row = idx >> 2;
        int ch = idx & 3;
        uint32_t so = (uint32_t)(row * (SSTR * 2) + ch * 16);
        size_t bo = (size_t)(n_base + row) * Kd + k0 + ch * 8;
        cp16(st + 2*ATILE + so, Bth + bo, 16);
        cp16(st + 3*ATILE + so, Btl + bo, 16);
    }
}

template<bool CONV, bool BIAS, bool SILU, bool RESID, bool OUTF32, bool OUTSPLIT>
__global__ __launch_bounds__(256)
void bmma_gemm(const bf16* __restrict__ Ah, const bf16* __restrict__ Al,
               const bf16* __restrict__ Bth, const bf16* __restrict__ Btl,
               float* __restrict__ Cf, bf16* __restrict__ Ch, bf16* __restrict__ Cl,
               int N, int Kd, const float* __restrict__ bias, const float* __restrict__ resid) {
    extern __shared__ __align__(16) uint8_t dsm[];
    const int tid = threadIdx.x;
    const int warp = tid >> 5, lane = tid & 31;
    const int g = lane >> 2, tg = lane & 3;
    const int wm = (warp >> 2) * 64;
    const int wn = (warp & 3) * 32;
    const int m_base = blockIdx.y * 128, n_base = blockIdx.x * 128;
    const uint32_t base0 = (uint32_t)__cvta_generic_to_shared(dsm);

    float acc[4][4][4];
    #pragma unroll
    for (int i = 0; i < 4; i++)
        #pragma unroll
        for (int j = 0; j < 4; j++) { acc[i][j][0]=0.f; acc[i][j][1]=0.f; acc[i][j][2]=0.f; acc[i][j][3]=0.f; }

    const uint32_t aRow = (uint32_t)(lane & 15);
    const uint32_t aChB = (uint32_t)((lane >> 4) * 16);
    const uint32_t bRow = (uint32_t)((lane & 7) + (lane >> 4) * 8);
    const uint32_t bChB = (uint32_t)(((lane >> 3) & 1) * 16);

    const int ntk = Kd / GBK;
    load_stage_A<CONV>(base0, 0, Ah, Al, Kd, m_base, tid);
    load_stage_B(base0, 0, Bth, Btl, Kd, n_base, tid);
    asm volatile("cp.async.commit_group;" ::: "memory");

    for (int it = 0; it < ntk; ++it) {
        asm volatile("cp.async.wait_group 0;" ::: "memory");
        __syncthreads();
        const uint32_t stg  = base0 + (uint32_t)(it & 1) * STAGE;
        const uint32_t nstg = base0 + (uint32_t)((it + 1) & 1) * STAGE;
        const bool more = (it + 1 < ntk);

        #pragma unroll
        for (int ks = 0; ks < 2; ks++) {
            const uint32_t kOffB = (uint32_t)(ks * 32);
            uint32_t Bh[4][2], Bl[4][2], Ahf[4][4], Alf[4][4];
            #pragma unroll
            for (int ntp = 0; ntp < 2; ntp++) {
                uint32_t addr = stg + 2*ATILE + (uint32_t)(wn + ntp*16 + bRow) * (SSTR*2) + kOffB + bChB;
                uint32_t tr[4];
                ldsm_x4(tr, addr);
                Bh[ntp*2][0]=tr[0]; Bh[ntp*2][1]=tr[1]; Bh[ntp*2+1][0]=tr[2]; Bh[ntp*2+1][1]=tr[3];
                ldsm_x4(tr, addr + ATILE);
                Bl[ntp*2][0]=tr[0]; Bl[ntp*2][1]=tr[1]; Bl[ntp*2+1][0]=tr[2]; Bl[ntp*2+1][1]=tr[3];
            }
            #pragma unroll
            for (int mt = 0; mt < 4; mt++)
                ldsm_x4(Ahf[mt], stg + (uint32_t)(wm + mt*16 + aRow) * (SSTR*2) + kOffB + aChB);
            // pass 1: Ah x Bl
            #pragma unroll
            for (int mt = 0; mt < 4; mt++)
                #pragma unroll
                for (int nt = 0; nt < 4; nt++)
                    mma_bf(acc[mt][nt], Ahf[mt], Bl[nt]);
            // mid-iteration prefetch, A half after pass 1 (ks==0)
            if (ks == 0 && more)
                load_stage_A<CONV>(nstg, (it + 1) * GBK, Ah, Al, Kd, m_base, tid);
            #pragma unroll
            for (int mt = 0; mt < 4; mt++)
                ldsm_x4(Alf[mt], stg + ATILE + (uint32_t)(wm + mt*16 + aRow) * (SSTR*2) + kOffB + aChB);
            // pass 2: Al x Bh
            #pragma unroll
            for (int mt = 0; mt < 4; mt++)
                #pragma unroll
                for (int nt = 0; nt < 4; nt++)
                    mma_bf(acc[mt][nt], Alf[mt], Bh[nt]);
            // mid-iteration prefetch, B half after pass 2 (ks==0)
            if (ks == 0 && more) {
                load_stage_B(nstg, (it + 1) * GBK, Bth, Btl, Kd, n_base, tid);
                asm volatile("cp.async.commit_group;" ::: "memory");
            }
            // pass 3: Ah x Bh
            #pragma unroll
            for (int mt = 0; mt < 4; mt++)
                #pragma unroll
                for (int nt = 0; nt < 4; nt++)
                    mma_bf(acc[mt][nt], Ahf[mt], Bh[nt]);
        }
    }

    // epilogue
    #pragma unroll
    for (int mt = 0; mt < 4; mt++) {
        #pragma unroll
        for (int nt = 0; nt < 4; nt++) {
            int col = n_base + wn + nt * 8 + tg * 2;
            #pragma unroll
            for (int half = 0; half < 2; half++) {
                int row = m_base + wm + mt * 16 + g + half * 8;
                float c0 = acc[mt][nt][half * 2 + 0];
                float c1 = acc[mt][nt][half * 2 + 1];
                if (BIAS) { c0 += bias[col]; c1 += bias[col + 1]; }
                if (SILU) {
                    c0 = c0 / (1.0f + __expf(-c0));
                    c1 = c1 / (1.0f + __expf(-c1));
                }
                if (RESID) {
                    float2 r = *reinterpret_cast<const float2*>(resid + (size_t)row * N + col);
                    c0 += r.x; c1 += r.y;
                }
                if (OUTF32) {
                    float2 o; o.x = c0; o.y = c1;
                    *reinterpret_cast<float2*>(Cf + (size_t)row * N + col) = o;
                }
                if (OUTSPLIT) {
                    bf16 h0, l0, h1, l1;
                    bf16_split(c0, h0, l0);
                    bf16_split(c1, h1, l1);
                    __nv_bfloat162 hp; hp.x = h0; hp.y = h1;
                    __nv_bfloat162 lp; lp.x = l0; lp.y = l1;
                    *reinterpret_cast<__nv_bfloat162*>(Ch + (size_t)row * N + col) = hp;
                    *reinterpret_cast<__nv_bfloat162*>(Cl + (size_t)row * N + col) = lp;
                }
            }
        }
    }
}

// ---------------- dt / scans (rope fused into scan_final) ----------------
__global__ void dt_kernel(const float* __restrict__ w_dt, const float* __restrict__ b_dt,
                          const float* __restrict__ dt_bias) {
    int m = blockIdx.x, nh = threadIdx.x >> 5, lane = threadIdx.x & 31;
    const bf16* hh = g_normh + (size_t)m * Hdim;
    const bf16* hl = g_norml + (size_t)m * Hdim;
    float s = 0.f;
    for (int k = lane; k < Hdim; k += 32)
        s += (__bfloat162float(hh[k]) + __bfloat162float(hl[k])) * w_dt[(size_t)k * NHdim + nh];
    #pragma unroll
    for (int o = 16; o; o >>= 1) s += __shfl_down_sync(0xffffffffu, s, o);
    if (lane == 0) {
        float x = s + b_dt[nh] + dt_bias[nh];
        g_dt[m * NHdim + nh] = fmaxf(x, 0.f) + log1pf(expf(-fabsf(x)));
    }
}
__global__ void p_scan_kernel(const float* __restrict__ A_log) {
    int warp = threadIdx.x >> 5, lane = threadIdx.x & 31;
    int b = warp >> 4, nh = warp & (NHdim - 1);
    float Anh = -expf(A_log[nh]);
    int t0 = lane * (Tdim / 32);
    float prod = 1.f;
    for (int i = 0; i < Tdim / 32; i++)
        prod *= expf(Anh * g_dt[(b * Tdim + t0 + i) * NHdim + nh]);
    float x = prod;
    #pragma unroll
    for (int o = 1; o < 32; o <<= 1) {
        float y = __shfl_up_sync(0xffffffffu, x, o);
        if (lane >= o) x *= y;
    }
    float excl = __shfl_up_sync(0xffffffffu, x, 1);
    if (lane == 0) excl = 1.f;
    float run = excl;
    float* prow = g_p + warp * Tdim;
    for (int i = 0; i < Tdim / 32; i++) {
        int t = t0 + i;
        run *= expf(Anh * g_dt[(b * Tdim + t) * NHdim + nh]);
        prow[t] = run;
    }
}
__global__ void scan_partial_kernel() {
    int blk = blockIdx.x, bnh = blk >> 6, c = blk & (NCHUNK - 1);
    int b = bnh >> 4, nh = bnh & (NHdim - 1), hd = threadIdx.x;
    const float* prow = g_p + bnh * Tdim;
    double s = 0.0;
    int t0 = c * CHUNK;
    for (int i = 0; i < CHUNK; i++) {
        int t = t0 + i, m = b * Tdim + t;
        float beta = g_dt[m * NHdim + nh], pv = prow[t];
        float v = g_qv[(size_t)m * (2*Hdim) + Hdim + nh * HDdim + hd];
        s += (double)((beta * v) / (pv + EPSf));
    }
    g_S[(size_t)blk * HDdim + hd] = s;
}
__global__ void scan_carry_kernel() {
    int bnh = blockIdx.x, hd = threadIdx.x;
    double carry = 0.0;
    for (int c = 0; c < NCHUNK; c++) {
        size_t idx = ((size_t)bnh * NCHUNK + c) * HDdim + hd;
        g_carry[idx] = carry;
        carry += g_S[idx];
    }
}
__global__ void scan_final_kernel(const int* __restrict__ pos_ids) {
    int blk = blockIdx.x, bnh = blk >> 6, c = blk & (NCHUNK - 1);
    int b = bnh >> 4, nh = bnh & (NHdim - 1), hd = threadIdx.x;
    const float* prow = g_p + bnh * Tdim;
    double s = g_carry[(size_t)blk * HDdim + hd];
    const float invf = g_invf[hd & 63];
    const bool even = (hd & 1) == 0;
    int t0 = c * CHUNK;
    for (int i = 0; i < CHUNK; i++) {
        int t = t0 + i, m = b * Tdim + t;
        float beta = g_dt[m * NHdim + nh], pv = prow[t];
        size_t qvbase = (size_t)m * (2*Hdim) + nh * HDdim + hd;
        float v = g_qv[qvbase + Hdim];
        s += (double)((beta * v) / (pv + EPSf));
        float state = (float)((double)pv * s);
        float qv = g_qv[qvbase];
        float qp = __shfl_xor_sync(0xffffffffu, qv, 1);
        float pos = (float)pos_ids[m];
        float ang = pos * invf;
        float ca = cosf(ang), sa = sinf(ang);
        float qr = even ? (qv * ca - qp * sa) : (qv * ca + qp * sa);
        float outv = qr * state;
        bf16 h, l; bf16_split(outv, h, l);
        size_t oi = (size_t)m * Hdim + nh * HDdim + hd;
        g_scanh[oi] = h; g_scanl[oi] = l;
    }
}

// ---------------- launch (two-stream fork/join) ----------------
extern "C" void kernel_launch(void* const* d_in, const int* in_sizes, int n_in,
                              void* d_out, int out_size) {
    const float* hidden  = (const float*)d_in[0];
    const int*   pos_ids = (const int*)  d_in[1];
    const float* conv_w  = (const float*)d_in[2];
    const float* conv_b  = (const float*)d_in[3];
    const float* wq      = (const float*)d_in[4];
    const float* wv      = (const float*)d_in[5];
    const float* w_dt    = (const float*)d_in[6];
    const float* b_dt    = (const float*)d_in[7];
    const float* A_log   = (const float*)d_in[8];
    const float* dt_bias = (const float*)d_in[9];
    const float* wo      = (const float*)d_in[10];
    const float* w1      = (const float*)d_in[11];
    const float* w2      = (const float*)d_in[12];
    const float* norm1_w = (const float*)d_in[13];
    const float* norm2_w = (const float*)d_in[14];
    float* out = (float*)d_out;

    bf16 *wcTh,*wcTl,*wqvTh,*wqvTl,*woTh,*woTl,*w1Th,*w1Tl,*w2Th,*w2Tl;
    bf16 *normh,*norml,*xh,*xl,*scanh,*scanl,*interh,*interl;
    float *pqv,*ph2;
    cudaGetSymbolAddress((void**)&wcTh, g_wcTh);     cudaGetSymbolAddress((void**)&wcTl, g_wcTl);
    cudaGetSymbolAddress((void**)&wqvTh, g_wqvTh);   cudaGetSymbolAddress((void**)&wqvTl, g_wqvTl);
    cudaGetSymbolAddress((void**)&woTh, g_woTh);     cudaGetSymbolAddress((void**)&woTl, g_woTl);
    cudaGetSymbolAddress((void**)&w1Th, g_w1Th);     cudaGetSymbolAddress((void**)&w1Tl, g_w1Tl);
    cudaGetSymbolAddress((void**)&w2Th, g_w2Th);     cudaGetSymbolAddress((void**)&w2Tl, g_w2Tl);
    cudaGetSymbolAddress((void**)&normh, g_normh);   cudaGetSymbolAddress((void**)&norml, g_norml);
    cudaGetSymbolAddress((void**)&xh, g_xh);         cudaGetSymbolAddress((void**)&xl, g_xl);
    cudaGetSymbolAddress((void**)&scanh, g_scanh);   cudaGetSymbolAddress((void**)&scanl, g_scanl);
    cudaGetSymbolAddress((void**)&interh, g_interh); cudaGetSymbolAddress((void**)&interl, g_interl);
    cudaGetSymbolAddress((void**)&pqv, g_qv);
    cudaGetSymbolAddress((void**)&ph2, g_h2);

    cudaFuncSetAttribute(bmma_gemm<true,true,false,false,false,true>,   cudaFuncAttributeMaxDynamicSharedMemorySize, DYN_SMEM);
    cudaFuncSetAttribute(bmma_gemm<false,false,false,false,true,false>, cudaFuncAttributeMaxDynamicSharedMemorySize, DYN_SMEM);
    cudaFuncSetAttribute(bmma_gemm<false,false,false,true,true,false>,  cudaFuncAttributeMaxDynamicSharedMemorySize, DYN_SMEM);
    cudaFuncSetAttribute(bmma_gemm<false,false,true,false,false,true>,  cudaFuncAttributeMaxDynamicSharedMemorySize, DYN_SMEM);

    // fork a side stream for weight prep + dt/p_scan (overlaps conv GEMM)
    cudaStream_t sB;
    cudaStreamCreateWithFlags(&sB, cudaStreamNonBlocking);
    cudaEvent_t eFork, eNorm, eJoin;
    cudaEventCreateWithFlags(&eFork, cudaEventDisableTiming);
    cudaEventCreateWithFlags(&eNorm, cudaEventDisableTiming);
    cudaEventCreateWithFlags(&eJoin, cudaEventDisableTiming);

    cudaEventRecord(eFork, 0);
    cudaStreamWaitEvent(sB, eFork, 0);

    // ---- side stream: independent weight prep ----
    init_invf_kernel<<<1, 64, 0, sB>>>();
    transpose_split_kernel<<<dim3(Hdim/32, Hdim/32), dim3(32,8), 0, sB>>>(wq, wqvTh, wqvTl, Hdim, Hdim);
    transpose_split_kernel<<<dim3(Hdim/32, Hdim/32), dim3(32,8), 0, sB>>>(
        wv, wqvTh + (size_t)Hdim*Hdim, wqvTl + (size_t)Hdim*Hdim, Hdim, Hdim);
    transpose_split_kernel<<<dim3(Hdim/32, Hdim/32), dim3(32,8), 0, sB>>>(wo, woTh, woTl, Hdim, Hdim);
    transpose_split_kernel<<<dim3(INTERd/32, Hdim/32), dim3(32,8), 0, sB>>>(w1, w1Th, w1Tl, Hdim, INTERd);
    transpose_split_kernel<<<dim3(Hdim/32, INTERd/32), dim3(32,8), 0, sB>>>(w2, w2Th, w2Tl, INTERd, Hdim);

    // ---- main stream: conv path ----
    pack_convw_split_kernel<<<dim3(24, Hdim), 256>>>(conv_w);
    rmsnorm_split_kernel<<<Mdim, 256>>>(hidden, norm1_w, normh, norml);
    cudaEventRecord(eNorm, 0);
    bmma_gemm<true,true,false,false,false,true><<<dim3(16,64), 256, DYN_SMEM>>>(
        normh, norml, wcTh, wcTl, nullptr, xh, xl, Hdim, KCONV*Hdim, conv_b, nullptr);

    // ---- side stream: dt chain (needs rmsnorm1 output) ----
    cudaStreamWaitEvent(sB, eNorm, 0);
    dt_kernel<<<Mdim, NHdim*32, 0, sB>>>(w_dt, b_dt, dt_bias);
    p_scan_kernel<<<1, 1024, 0, sB>>>(A_log);
    cudaEventRecord(eJoin, sB);

    // ---- join before qv GEMM ----
    cudaStreamWaitEvent(0, eJoin, 0);

    // merged q|v GEMM: N = 4096
    bmma_gemm<false,false,false,false,true,false><<<dim3(32,64), 256, DYN_SMEM>>>(
        xh, xl, wqvTh, wqvTl, pqv, nullptr, nullptr, 2*Hdim, Hdim, nullptr, nullptr);
    scan_partial_kernel<<<Bdim*NHdim*NCHUNK, HDdim>>>();
    scan_carry_kernel<<<Bdim*NHdim, HDdim>>>();
    scan_final_kernel<<<Bdim*NHdim*NCHUNK, HDdim>>>(pos_ids);
    bmma_gemm<false,false,false,true,true,false><<<dim3(16,64), 256, DYN_SMEM>>>(
        scanh, scanl, woTh, woTl, ph2, nullptr, nullptr, Hdim, Hdim, nullptr, hidden);

    // mlp branch
    rmsnorm_split_kernel<<<Mdim, 256>>>(ph2, norm2_w, normh, norml);
    bmma_gemm<false,false,true,false,false,true><<<dim3(64,64), 256, DYN_SMEM>>>(
        normh, norml, w1Th, w1Tl, nullptr, interh, interl, INTERd, Hdim, nullptr, nullptr);
    bmma_gemm<false,false,false,true,true,false><<<dim3(16,64), 256, DYN_SMEM>>>(
        interh, interl, w2Th, w2Tl, out, nullptr, nullptr, Hdim, INTERd, nullptr, ph2);
}

// round 14
// speedup vs baseline: 1.1827x; 1.0348x over previous
#include <cuda_runtime.h>
#include <cuda_bf16.h>
#include <math.h>
#include <stdint.h>

#define Bdim   2
#define Tdim   4096
#define Hdim   2048
#define NHdim  16
#define HDdim  128
#define Mdim   8192
#define INTERd 8192
#define KCONV  3
#define EPSf   1e-6f
#define NCHUNK 64
#define CHUNK  64

// GEMM tiling (proven): block 128x128, BK=32 bf16, 2-stage, warp 64x32
#define GBK   32
#define SSTR  40
#define ATILE (128 * SSTR * 2)
#define STAGE (4 * ATILE)
#define DYN_SMEM (2 * STAGE)        // 81920 B -> 2 CTAs/SM

typedef __nv_bfloat16 bf16;

// ---------------- device scratch ----------------
__device__ bf16 g_wcTh[(size_t)Hdim * (KCONV*Hdim)];
__device__ bf16 g_wcTl[(size_t)Hdim * (KCONV*Hdim)];
__device__ bf16 g_wqvTh[(size_t)2 * Hdim * Hdim];   // rows 0..2047 wq^T, 2048..4095 wv^T
__device__ bf16 g_wqvTl[(size_t)2 * Hdim * Hdim];
__device__ bf16 g_woTh[(size_t)Hdim * Hdim];
__device__ bf16 g_woTl[(size_t)Hdim * Hdim];
__device__ bf16 g_w1Th[(size_t)INTERd * Hdim];
__device__ bf16 g_w1Tl[(size_t)INTERd * Hdim];
__device__ bf16 g_w2Th[(size_t)Hdim * INTERd];
__device__ bf16 g_w2Tl[(size_t)Hdim * INTERd];
__device__ bf16 g_normh[(size_t)Mdim * Hdim];
__device__ bf16 g_norml[(size_t)Mdim * Hdim];
__device__ bf16 g_xh[(size_t)Mdim * Hdim];
__device__ bf16 g_xl[(size_t)Mdim * Hdim];
__device__ bf16 g_scanh[(size_t)Mdim * Hdim];
__device__ bf16 g_scanl[(size_t)Mdim * Hdim];
__device__ bf16 g_interh[(size_t)Mdim * INTERd];
__device__ bf16 g_interl[(size_t)Mdim * INTERd];
__device__ float  g_qv[(size_t)Mdim * 2 * Hdim];    // [M][4096]: 0..2047=q, 2048..4095=v
__device__ float  g_h2[(size_t)Mdim * Hdim];
__device__ float  g_dt[Mdim * NHdim];
__device__ float  g_p[Bdim * NHdim * Tdim];
__device__ double g_S[Bdim * NHdim * NCHUNK * HDdim];
__device__ double g_carry[Bdim * NHdim * NCHUNK * HDdim];
__device__ float  g_invf[HDdim / 2];

// ---------------- helpers ----------------
__device__ __forceinline__ void cp16(uint32_t dst, const void* src, int sz) {
    asm volatile("cp.async.cg.shared.global [%0], [%1], 16, %2;\n" :: "r"(dst), "l"(src), "r"(sz));
}
__device__ __forceinline__ void ldsm_x4(uint32_t* r, uint32_t addr) {
    asm volatile("ldmatrix.sync.aligned.m8n8.x4.shared.b16 {%0,%1,%2,%3}, [%4];"
                 : "=r"(r[0]), "=r"(r[1]), "=r"(r[2]), "=r"(r[3]) : "r"(addr));
}
__device__ __forceinline__ void mma_bf(float* c, const uint32_t* a, const uint32_t* b) {
    asm volatile("mma.sync.aligned.m16n8k16.row.col.f32.bf16.bf16.f32 "
                 "{%0,%1,%2,%3}, {%4,%5,%6,%7}, {%8,%9}, {%0,%1,%2,%3};"
                 : "+f"(c[0]), "+f"(c[1]), "+f"(c[2]), "+f"(c[3])
                 : "r"(a[0]), "r"(a[1]), "r"(a[2]), "r"(a[3]), "r"(b[0]), "r"(b[1]));
}
__device__ __forceinline__ void bf16_split(float v, bf16& h, bf16& l) {
    h = __float2bfloat16(v);
    l = __float2bfloat16(v - __bfloat162float(h));
}

// ---------------- init / weight prep ----------------
__global__ void init_invf_kernel() {
    int j = threadIdx.x;
    if (j < HDdim / 2) g_invf[j] = (float)exp(-((double)j / 64.0) * log(10000.0));
}
__global__ void pack_convw_split_kernel(const float* __restrict__ conv_w) {
    int inner = blockIdx.x * 256 + threadIdx.x;
    int o = blockIdx.y;
    if (inner >= KCONV * Hdim) return;
    int k = inner >> 11, i = inner & (Hdim - 1);
    float v = conv_w[((size_t)o * Hdim + i) * KCONV + k];
    bf16 h, l; bf16_split(v, h, l);
    size_t oi = (size_t)o * (KCONV * Hdim) + inner;
    g_wcTh[oi] = h; g_wcTl[oi] = l;
}
__global__ void transpose_split_kernel(const float* __restrict__ in, bf16* __restrict__ oh,
                                       bf16* __restrict__ ol, int R, int C) {
    __shared__ float tile[32][33];
    int c0 = blockIdx.x * 32, r0 = blockIdx.y * 32;
    int x = threadIdx.x, y = threadIdx.y;
    #pragma unroll
    for (int j = 0; j < 32; j += 8) tile[y + j][x] = in[(size_t)(r0 + y + j) * C + c0 + x];
    __syncthreads();
    #pragma unroll
    for (int j = 0; j < 32; j += 8) {
        bf16 h, l; bf16_split(tile[x][y + j], h, l);
        size_t oi = (size_t)(c0 + y + j) * R + r0 + x;
        oh[oi] = h; ol[oi] = l;
    }
}

// ---------------- rmsnorm + split ----------------
__global__ void rmsnorm_split_kernel(const float* __restrict__ x, const float* __restrict__ w,
                                     bf16* __restrict__ yh, bf16* __restrict__ yl) {
    int m = blockIdx.x, t = threadIdx.x;
    const float4* xr = reinterpret_cast<const float4*>(x + (size_t)m * Hdim);
    const float4* wr = reinterpret_cast<const float4*>(w);
    float4 v0 = xr[t], v1 = xr[t + 256];
    float ss = v0.x*v0.x + v0.y*v0.y + v0.z*v0.z + v0.w*v0.w
             + v1.x*v1.x + v1.y*v1.y + v1.z*v1.z + v1.w*v1.w;
    __shared__ float red[8];
    #pragma unroll
    for (int o = 16; o; o >>= 1) ss += __shfl_down_sync(0xffffffffu, ss, o);
    if ((t & 31) == 0) red[t >> 5] = ss;
    __syncthreads();
    if (t < 32) {
        float s = (t < 8) ? red[t] : 0.f;
        #pragma unroll
        for (int o = 4; o; o >>= 1) s += __shfl_down_sync(0xffffffffu, s, o);
        if (t == 0) red[0] = s;
    }
    __syncthreads();
    float sc = rsqrtf(red[0] * (1.0f / Hdim) + EPSf);
    float4 w0 = wr[t], w1 = wr[t + 256];
    float o[8] = { v0.x*sc*w0.x, v0.y*sc*w0.y, v0.z*sc*w0.z, v0.w*sc*w0.w,
                   v1.x*sc*w1.x, v1.y*sc*w1.y, v1.z*sc*w1.z, v1.w*sc*w1.w };
    size_t base = (size_t)m * Hdim;
    bf16 hh[8], ll[8];
    #pragma unroll
    for (int i = 0; i < 8; i++) bf16_split(o[i], hh[i], ll[i]);
    *reinterpret_cast<uint2*>(yh + base + t*4)       = *reinterpret_cast<uint2*>(&hh[0]);
    *reinterpret_cast<uint2*>(yh + base + (t+256)*4) = *reinterpret_cast<uint2*>(&hh[4]);
    *reinterpret_cast<uint2*>(yl + base + t*4)       = *reinterpret_cast<uint2*>(&ll[0]);
    *reinterpret_cast<uint2*>(yl + base + (t+256)*4) = *reinterpret_cast<uint2*>(&ll[4]);
}

// =====================================================================
// 3x-bf16 mma.sync GEMM: loads split into A/B halves, issued mid-iteration.
// =====================================================================
template<bool CONV>
__device__ __forceinline__ void load_stage_A(uint32_t st, int k0,
    const bf16* __restrict__ Ah, const bf16* __restrict__ Al,
    int Kd, int m_base, int tid) {
    int kidx = 0, irow = 0;
    if (CONV) { kidx = k0 >> 11; irow = k0 & (Hdim - 1); }
    #pragma unroll
    for (int h = 0; h < 2; h++) {
        int idx = tid + h * 256;
        int row = idx >> 2;
        int ch = idx & 3;
        uint32_t so = (uint32_t)(row * (SSTR * 2) + ch * 16);
        if (CONV) {
            int gm = m_base + row, tp = gm & (Tdim - 1);
            int ok = (tp - 2 + kidx) >= 0;
            size_t ao = (size_t)(ok ? gm - 2 + kidx : 0) * Hdim + irow + ch * 8;
            cp16(st + so,         Ah + ao, ok ? 16 : 0);
            cp16(st + ATILE + so, Al + ao, ok ? 16 : 0);
        } else {
            size_t ao = (size_t)(m_base + row) * Kd + k0 + ch * 8;
            cp16(st + so,         Ah + ao, 16);
            cp16(st + ATILE + so, Al + ao, 16);
        }
    }
}
__device__ __forceinline__ void load_stage_B(uint32_t st, int k0,
    const bf16* __restrict__ Bth, const bf16* __restrict__ Btl,
    int Kd, int n_base, int tid) {
    #pragma unroll
    for (int h = 0; h < 2; h++) {
        int idx = tid + h * 256;
        int row = idx >> 2;
        int ch = idx & 3;
        uint32_t so = (uint32_t)(row * (SSTR * 2) + ch * 16);
        size_t bo = (size_t)(n_base + row) * Kd + k0 + ch * 8;
        cp16(st + 2*ATILE + so, Bth + bo, 16);
        cp16(st + 3*ATILE + so, Btl + bo, 16);
    }
}

template<bool CONV, bool BIAS, bool SILU, bool RESID, bool OUTF32, bool OUTSPLIT>
__global__ __launch_bounds__(256)
void bmma_gemm(const bf16* __restrict__ Ah, const bf16* __restrict__ Al,
               const bf16* __restrict__ Bth, const bf16* __restrict__ Btl,
               float* __restrict__ Cf, bf16* __restrict__ Ch, bf16* __restrict__ Cl,
               int N, int Kd, const float* __restrict__ bias, const float* __restrict__ resid) {
    extern __shared__ __align__(16) uint8_t dsm[];
    const int tid = threadIdx.x;
    const int warp = tid >> 5, lane = tid & 31;
    const int g = lane >> 2, tg = lane & 3;
    const int wm = (warp >> 2) * 64;
    const int wn = (warp & 3) * 32;
    const int m_base = blockIdx.y * 128, n_base = blockIdx.x * 128;
    const uint32_t base0 = (uint32_t)__cvta_generic_to_shared(dsm);

    float acc[4][4][4];
    #pragma unroll
    for (int i = 0; i < 4; i++)
        #pragma unroll
        for (int j = 0; j < 4; j++) { acc[i][j][0]=0.f; acc[i][j][1]=0.f; acc[i][j][2]=0.f; acc[i][j][3]=0.f; }

    const uint32_t aRow = (uint32_t)(lane & 15);
    const uint32_t aChB = (uint32_t)((lane >> 4) * 16);
    const uint32_t bRow = (uint32_t)((lane & 7) + (lane >> 4) * 8);
    const uint32_t bChB = (uint32_t)(((lane >> 3) & 1) * 16);

    const int ntk = Kd / GBK;
    load_stage_A<CONV>(base0, 0, Ah, Al, Kd, m_base, tid);
    load_stage_B(base0, 0, Bth, Btl, Kd, n_base, tid);
    asm volatile("cp.async.commit_group;" ::: "memory");

    for (int it = 0; it < ntk; ++it) {
        asm volatile("cp.async.wait_group 0;" ::: "memory");
        __syncthreads();
        const uint32_t stg  = base0 + (uint32_t)(it & 1) * STAGE;
        const uint32_t nstg = base0 + (uint32_t)((it + 1) & 1) * STAGE;
        const bool more = (it + 1 < ntk);

        #pragma unroll
        for (int ks = 0; ks < 2; ks++) {
            const uint32_t kOffB = (uint32_t)(ks * 32);
            uint32_t Bh[4][2], Bl[4][2], Ahf[4][4], Alf[4][4];
            #pragma unroll
            for (int ntp = 0; ntp < 2; ntp++) {
                uint32_t addr = stg + 2*ATILE + (uint32_t)(wn + ntp*16 + bRow) * (SSTR*2) + kOffB + bChB;
                uint32_t tr[4];
                ldsm_x4(tr, addr);
                Bh[ntp*2][0]=tr[0]; Bh[ntp*2][1]=tr[1]; Bh[ntp*2+1][0]=tr[2]; Bh[ntp*2+1][1]=tr[3];
                ldsm_x4(tr, addr + ATILE);
                Bl[ntp*2][0]=tr[0]; Bl[ntp*2][1]=tr[1]; Bl[ntp*2+1][0]=tr[2]; Bl[ntp*2+1][1]=tr[3];
            }
            #pragma unroll
            for (int mt = 0; mt < 4; mt++)
                ldsm_x4(Ahf[mt], stg + (uint32_t)(wm + mt*16 + aRow) * (SSTR*2) + kOffB + aChB);
            // pass 1: Ah x Bl
            #pragma unroll
            for (int mt = 0; mt < 4; mt++)
                #pragma unroll
                for (int nt = 0; nt < 4; nt++)
                    mma_bf(acc[mt][nt], Ahf[mt], Bl[nt]);
            if (ks == 0 && more)
                load_stage_A<CONV>(nstg, (it + 1) * GBK, Ah, Al, Kd, m_base, tid);
            #pragma unroll
            for (int mt = 0; mt < 4; mt++)
                ldsm_x4(Alf[mt], stg + ATILE + (uint32_t)(wm + mt*16 + aRow) * (SSTR*2) + kOffB + aChB);
            // pass 2: Al x Bh
            #pragma unroll
            for (int mt = 0; mt < 4; mt++)
                #pragma unroll
                for (int nt = 0; nt < 4; nt++)
                    mma_bf(acc[mt][nt], Alf[mt], Bh[nt]);
            if (ks == 0 && more) {
                load_stage_B(nstg, (it + 1) * GBK, Bth, Btl, Kd, n_base, tid);
                asm volatile("cp.async.commit_group;" ::: "memory");
            }
            // pass 3: Ah x Bh
            #pragma unroll
            for (int mt = 0; mt < 4; mt++)
                #pragma unroll
                for (int nt = 0; nt < 4; nt++)
                    mma_bf(acc[mt][nt], Ahf[mt], Bh[nt]);
        }
    }

    // epilogue
    #pragma unroll
    for (int mt = 0; mt < 4; mt++) {
        #pragma unroll
        for (int nt = 0; nt < 4; nt++) {
            int col = n_base + wn + nt * 8 + tg * 2;
            #pragma unroll
            for (int half = 0; half < 2; half++) {
                int row = m_base + wm + mt * 16 + g + half * 8;
                float c0 = acc[mt][nt][half * 2 + 0];
                float c1 = acc[mt][nt][half * 2 + 1];
                if (BIAS) { c0 += bias[col]; c1 += bias[col + 1]; }
                if (SILU) {
                    c0 = c0 / (1.0f + __expf(-c0));
                    c1 = c1 / (1.0f + __expf(-c1));
                }
                if (RESID) {
                    float2 r = *reinterpret_cast<const float2*>(resid + (size_t)row * N + col);
                    c0 += r.x; c1 += r.y;
                }
                if (OUTF32) {
                    float2 o; o.x = c0; o.y = c1;
                    *reinterpret_cast<float2*>(Cf + (size_t)row * N + col) = o;
                }
                if (OUTSPLIT) {
                    bf16 h0, l0, h1, l1;
                    bf16_split(c0, h0, l0);
                    bf16_split(c1, h1, l1);
                    __nv_bfloat162 hp; hp.x = h0; hp.y = h1;
                    __nv_bfloat162 lp; lp.x = l0; lp.y = l1;
                    *reinterpret_cast<__nv_bfloat162*>(Ch + (size_t)row * N + col) = hp;
                    *reinterpret_cast<__nv_bfloat162*>(Cl + (size_t)row * N + col) = lp;
                }
            }
        }
    }
}

// ---------------- dt / scans (rope fused into scan_final) ----------------
__global__ void dt_kernel(const float* __restrict__ w_dt, const float* __restrict__ b_dt,
                          const float* __restrict__ dt_bias) {
    int m = blockIdx.x, nh = threadIdx.x >> 5, lane = threadIdx.x & 31;
    const bf16* hh = g_normh + (size_t)m * Hdim;
    const bf16* hl = g_norml + (size_t)m * Hdim;
    float s = 0.f;
    for (int k = lane; k < Hdim; k += 32)
        s += (__bfloat162float(hh[k]) + __bfloat162float(hl[k])) * w_dt[(size_t)k * NHdim + nh];
    #pragma unroll
    for (int o = 16; o; o >>= 1) s += __shfl_down_sync(0xffffffffu, s, o);
    if (lane == 0) {
        float x = s + b_dt[nh] + dt_bias[nh];
        g_dt[m * NHdim + nh] = fmaxf(x, 0.f) + log1pf(expf(-fabsf(x)));
    }
}
__global__ void p_scan_kernel(const float* __restrict__ A_log) {
    int warp = threadIdx.x >> 5, lane = threadIdx.x & 31;
    int b = warp >> 4, nh = warp & (NHdim - 1);
    float Anh = -expf(A_log[nh]);
    int t0 = lane * (Tdim / 32);
    float prod = 1.f;
    for (int i = 0; i < Tdim / 32; i++)
        prod *= expf(Anh * g_dt[(b * Tdim + t0 + i) * NHdim + nh]);
    float x = prod;
    #pragma unroll
    for (int o = 1; o < 32; o <<= 1) {
        float y = __shfl_up_sync(0xffffffffu, x, o);
        if (lane >= o) x *= y;
    }
    float excl = __shfl_up_sync(0xffffffffu, x, 1);
    if (lane == 0) excl = 1.f;
    float run = excl;
    float* prow = g_p + warp * Tdim;
    for (int i = 0; i < Tdim / 32; i++) {
        int t = t0 + i;
        run *= expf(Anh * g_dt[(b * Tdim + t) * NHdim + nh]);
        prow[t] = run;
    }
}
__global__ void scan_partial_kernel() {
    int blk = blockIdx.x, bnh = blk >> 6, c = blk & (NCHUNK - 1);
    int b = bnh >> 4, nh = bnh & (NHdim - 1), hd = threadIdx.x;
    const float* prow = g_p + bnh * Tdim;
    double s = 0.0;
    int t0 = c * CHUNK;
    for (int i = 0; i < CHUNK; i++) {
        int t = t0 + i, m = b * Tdim + t;
        float beta = g_dt[m * NHdim + nh], pv = prow[t];
        float v = g_qv[(size_t)m * (2*Hdim) + Hdim + nh * HDdim + hd];
        s += (double)((beta * v) / (pv + EPSf));
    }
    g_S[(size_t)blk * HDdim + hd] = s;
}
__global__ void scan_carry_kernel() {
    int bnh = blockIdx.x, hd = threadIdx.x;
    double carry = 0.0;
    for (int c = 0; c < NCHUNK; c++) {
        size_t idx = ((size_t)bnh * NCHUNK + c) * HDdim + hd;
        g_carry[idx] = carry;
        carry += g_S[idx];
    }
}
__global__ void scan_final_kernel(const int* __restrict__ pos_ids) {
    int blk = blockIdx.x, bnh = blk >> 6, c = blk & (NCHUNK - 1);
    int b = bnh >> 4, nh = bnh & (NHdim - 1), hd = threadIdx.x;
    const float* prow = g_p + bnh * Tdim;
    double s = g_carry[(size_t)blk * HDdim + hd];
    const float invf = g_invf[hd & 63];
    const bool even = (hd & 1) == 0;
    int t0 = c * CHUNK;
    for (int i = 0; i < CHUNK; i++) {
        int t = t0 + i, m = b * Tdim + t;
        float beta = g_dt[m * NHdim + nh], pv = prow[t];
        size_t qvbase = (size_t)m * (2*Hdim) + nh * HDdim + hd;
        float v = g_qv[qvbase + Hdim];
        s += (double)((beta * v) / (pv + EPSf));
        float state = (float)((double)pv * s);
        float qv = g_qv[qvbase];
        float qp = __shfl_xor_sync(0xffffffffu, qv, 1);
        float pos = (float)pos_ids[m];
        float ang = pos * invf;
        float ca = cosf(ang), sa = sinf(ang);
        float qr = even ? (qv * ca - qp * sa) : (qv * ca + qp * sa);
        float outv = qr * state;
        bf16 h, l; bf16_split(outv, h, l);
        size_t oi = (size_t)m * Hdim + nh * HDdim + hd;
        g_scanh[oi] = h; g_scanl[oi] = l;
    }
}

// ---------------- launch (two-stream fork/join, v-first) ----------------
extern "C" void kernel_launch(void* const* d_in, const int* in_sizes, int n_in,
                              void* d_out, int out_size) {
    const float* hidden  = (const float*)d_in[0];
    const int*   pos_ids = (const int*)  d_in[1];
    const float* conv_w  = (const float*)d_in[2];
    const float* conv_b  = (const float*)d_in[3];
    const float* wq      = (const float*)d_in[4];
    const float* wv      = (const float*)d_in[5];
    const float* w_dt    = (const float*)d_in[6];
    const float* b_dt    = (const float*)d_in[7];
    const float* A_log   = (const float*)d_in[8];
    const float* dt_bias = (const float*)d_in[9];
    const float* wo      = (const float*)d_in[10];
    const float* w1      = (const float*)d_in[11];
    const float* w2      = (const float*)d_in[12];
    const float* norm1_w = (const float*)d_in[13];
    const float* norm2_w = (const float*)d_in[14];
    float* out = (float*)d_out;

    bf16 *wcTh,*wcTl,*wqvTh,*wqvTl,*woTh,*woTl,*w1Th,*w1Tl,*w2Th,*w2Tl;
    bf16 *normh,*norml,*xh,*xl,*scanh,*scanl,*interh,*interl;
    float *pqv,*ph2;
    cudaGetSymbolAddress((void**)&wcTh, g_wcTh);     cudaGetSymbolAddress((void**)&wcTl, g_wcTl);
    cudaGetSymbolAddress((void**)&wqvTh, g_wqvTh);   cudaGetSymbolAddress((void**)&wqvTl, g_wqvTl);
    cudaGetSymbolAddress((void**)&woTh, g_woTh);     cudaGetSymbolAddress((void**)&woTl, g_woTl);
    cudaGetSymbolAddress((void**)&w1Th, g_w1Th);     cudaGetSymbolAddress((void**)&w1Tl, g_w1Tl);
    cudaGetSymbolAddress((void**)&w2Th, g_w2Th);     cudaGetSymbolAddress((void**)&w2Tl, g_w2Tl);
    cudaGetSymbolAddress((void**)&normh, g_normh);   cudaGetSymbolAddress((void**)&norml, g_norml);
    cudaGetSymbolAddress((void**)&xh, g_xh);         cudaGetSymbolAddress((void**)&xl, g_xl);
    cudaGetSymbolAddress((void**)&scanh, g_scanh);   cudaGetSymbolAddress((void**)&scanl, g_scanl);
    cudaGetSymbolAddress((void**)&interh, g_interh); cudaGetSymbolAddress((void**)&interl, g_interl);
    cudaGetSymbolAddress((void**)&pqv, g_qv);
    cudaGetSymbolAddress((void**)&ph2, g_h2);

    cudaFuncSetAttribute(bmma_gemm<true,true,false,false,false,true>,   cudaFuncAttributeMaxDynamicSharedMemorySize, DYN_SMEM);
    cudaFuncSetAttribute(bmma_gemm<false,false,false,false,true,false>, cudaFuncAttributeMaxDynamicSharedMemorySize, DYN_SMEM);
    cudaFuncSetAttribute(bmma_gemm<false,false,false,true,true,false>,  cudaFuncAttributeMaxDynamicSharedMemorySize, DYN_SMEM);
    cudaFuncSetAttribute(bmma_gemm<false,false,true,false,false,true>,  cudaFuncAttributeMaxDynamicSharedMemorySize, DYN_SMEM);

    cudaStream_t sB;
    cudaStreamCreateWithFlags(&sB, cudaStreamNonBlocking);
    cudaEvent_t eFork, ePack, eNorm, eV, eScan;
    cudaEventCreateWithFlags(&eFork, cudaEventDisableTiming);
    cudaEventCreateWithFlags(&ePack, cudaEventDisableTiming);
    cudaEventCreateWithFlags(&eNorm, cudaEventDisableTiming);
    cudaEventCreateWithFlags(&eV,    cudaEventDisableTiming);
    cudaEventCreateWithFlags(&eScan, cudaEventDisableTiming);

    cudaEventRecord(eFork, 0);
    cudaStreamWaitEvent(sB, eFork, 0);

    // ---- side stream: conv pack (needed by conv GEMM), then all transposes ----
    pack_convw_split_kernel<<<dim3(24, Hdim), 256, 0, sB>>>(conv_w);
    cudaEventRecord(ePack, sB);
    init_invf_kernel<<<1, 64, 0, sB>>>();
    transpose_split_kernel<<<dim3(Hdim/32, Hdim/32), dim3(32,8), 0, sB>>>(wq, wqvTh, wqvTl, Hdim, Hdim);
    transpose_split_kernel<<<dim3(Hdim/32, Hdim/32), dim3(32,8), 0, sB>>>(
        wv, wqvTh + (size_t)Hdim*Hdim, wqvTl + (size_t)Hdim*Hdim, Hdim, Hdim);
    transpose_split_kernel<<<dim3(Hdim/32, Hdim/32), dim3(32,8), 0, sB>>>(wo, woTh, woTl, Hdim, Hdim);
    transpose_split_kernel<<<dim3(INTERd/32, Hdim/32), dim3(32,8), 0, sB>>>(w1, w1Th, w1Tl, Hdim, INTERd);
    transpose_split_kernel<<<dim3(Hdim/32, INTERd/32), dim3(32,8), 0, sB>>>(w2, w2Th, w2Tl, INTERd, Hdim);

    // ---- main stream: rmsnorm1 (overlaps pack/transposes), then conv GEMM ----
    rmsnorm_split_kernel<<<Mdim, 256>>>(hidden, norm1_w, normh, norml);
    cudaEventRecord(eNorm, 0);
    cudaStreamWaitEvent(0, ePack, 0);
    bmma_gemm<true,true,false,false,false,true><<<dim3(16,64), 256, DYN_SMEM>>>(
        normh, norml, wcTh, wcTl, nullptr, xh, xl, Hdim, KCONV*Hdim, conv_b, nullptr);

    // ---- side stream: dt chain (needs rmsnorm1 output) ----
    cudaStreamWaitEvent(sB, eNorm, 0);
    dt_kernel<<<Mdim, NHdim*32, 0, sB>>>(w_dt, b_dt, dt_bias);
    p_scan_kernel<<<1, 1024, 0, sB>>>(A_log);

    // ---- main: v GEMM first (cols 2048..4095 of g_qv via pointer offset) ----
    bmma_gemm<false,false,false,false,true,false><<<dim3(16,64), 256, DYN_SMEM>>>(
        xh, xl, wqvTh + (size_t)Hdim*Hdim, wqvTl + (size_t)Hdim*Hdim,
        pqv + Hdim, nullptr, nullptr, 2*Hdim, Hdim, nullptr, nullptr);
    cudaEventRecord(eV, 0);
    // ---- main: q GEMM (cols 0..2047) ----
    bmma_gemm<false,false,false,false,true,false><<<dim3(16,64), 256, DYN_SMEM>>>(
        xh, xl, wqvTh, wqvTl, pqv, nullptr, nullptr, 2*Hdim, Hdim, nullptr, nullptr);

    // ---- side: scan partial+carry under the q GEMM ----
    cudaStreamWaitEvent(sB, eV, 0);
    scan_partial_kernel<<<Bdim*NHdim*NCHUNK, HDdim, 0, sB>>>();
    scan_carry_kernel<<<Bdim*NHdim, HDdim, 0, sB>>>();
    cudaEventRecord(eScan, sB);

    // ---- join: scan_final needs q (main) + carry (side) ----
    cudaStreamWaitEvent(0, eScan, 0);
    scan_final_kernel<<<Bdim*NHdim*NCHUNK, HDdim>>>(pos_ids);
    bmma_gemm<false,false,false,true,true,false><<<dim3(16,64), 256, DYN_SMEM>>>(
        scanh, scanl, woTh, woTl, ph2, nullptr, nullptr, Hdim, Hdim, nullptr, hidden);

    // mlp branch
    rmsnorm_split_kernel<<<Mdim, 256>>>(ph2, norm2_w, normh, norml);
    bmma_gemm<false,false,true,false,false,true><<<dim3(64,64), 256, DYN_SMEM>>>(
        normh, norml, w1Th, w1Tl, nullptr, interh, interl, INTERd, Hdim, nullptr, nullptr);
    bmma_gemm<false,false,false,true,true,false><<<dim3(16,64), 256, DYN_SMEM>>>(
        interh, interl, w2Th, w2Tl, out, nullptr, nullptr, Hdim, INTERd, nullptr, ph2);
}

// round 15
// speedup vs baseline: 1.1847x; 1.0017x over previous
#include <cuda_runtime.h>
#include <cuda_bf16.h>
#include <math.h>
#include <stdint.h>

#define Bdim   2
#define Tdim   4096
#define Hdim   2048
#define NHdim  16
#define HDdim  128
#define Mdim   8192
#define INTERd 8192
#define KCONV  3
#define EPSf   1e-6f
#define NCHUNK 64
#define CHUNK  64

// GEMM tiling (proven): block 128x128, BK=32 bf16, 2-stage, warp 64x32
#define GBK   32
#define SSTR  40
#define ATILE (128 * SSTR * 2)
#define STAGE (4 * ATILE)
#define DYN_SMEM (2 * STAGE)        // 81920 B -> 2 CTAs/SM

typedef __nv_bfloat16 bf16;

// ---------------- device scratch ----------------
__device__ bf16 g_wcTh[(size_t)Hdim * (KCONV*Hdim)];
__device__ bf16 g_wcTl[(size_t)Hdim * (KCONV*Hdim)];
__device__ bf16 g_wqvTh[(size_t)2 * Hdim * Hdim];   // rows 0..2047 wq^T, 2048..4095 wv^T
__device__ bf16 g_wqvTl[(size_t)2 * Hdim * Hdim];
__device__ bf16 g_woTh[(size_t)Hdim * Hdim];
__device__ bf16 g_woTl[(size_t)Hdim * Hdim];
__device__ bf16 g_w1Th[(size_t)INTERd * Hdim];
__device__ bf16 g_w1Tl[(size_t)INTERd * Hdim];
__device__ bf16 g_w2Th[(size_t)Hdim * INTERd];
__device__ bf16 g_w2Tl[(size_t)Hdim * INTERd];
__device__ bf16 g_normh[(size_t)Mdim * Hdim];
__device__ bf16 g_norml[(size_t)Mdim * Hdim];
__device__ bf16 g_xh[(size_t)Mdim * Hdim];
__device__ bf16 g_xl[(size_t)Mdim * Hdim];
__device__ bf16 g_scanh[(size_t)Mdim * Hdim];
__device__ bf16 g_scanl[(size_t)Mdim * Hdim];
__device__ bf16 g_interh[(size_t)Mdim * INTERd];
__device__ bf16 g_interl[(size_t)Mdim * INTERd];
__device__ float  g_qv[(size_t)Mdim * 2 * Hdim];    // [M][4096]: 0..2047=q, 2048..4095=v
__device__ float  g_h2[(size_t)Mdim * Hdim];
__device__ float  g_dt[Mdim * NHdim];
__device__ float  g_p[Bdim * NHdim * Tdim];
__device__ double g_S[Bdim * NHdim * NCHUNK * HDdim];
__device__ double g_carry[Bdim * NHdim * NCHUNK * HDdim];
__device__ float  g_invf[HDdim / 2];
__device__ float  g_rcos[(size_t)Mdim * 64];        // RoPE table [m][j]
__device__ float  g_rsin[(size_t)Mdim * 64];

// ---------------- helpers ----------------
__device__ __forceinline__ void cp16(uint32_t dst, const void* src, int sz) {
    asm volatile("cp.async.cg.shared.global [%0], [%1], 16, %2;\n" :: "r"(dst), "l"(src), "r"(sz));
}
__device__ __forceinline__ void ldsm_x4(uint32_t* r, uint32_t addr) {
    asm volatile("ldmatrix.sync.aligned.m8n8.x4.shared.b16 {%0,%1,%2,%3}, [%4];"
                 : "=r"(r[0]), "=r"(r[1]), "=r"(r[2]), "=r"(r[3]) : "r"(addr));
}
__device__ __forceinline__ void mma_bf(float* c, const uint32_t* a, const uint32_t* b) {
    asm volatile("mma.sync.aligned.m16n8k16.row.col.f32.bf16.bf16.f32 "
                 "{%0,%1,%2,%3}, {%4,%5,%6,%7}, {%8,%9}, {%0,%1,%2,%3};"
                 : "+f"(c[0]), "+f"(c[1]), "+f"(c[2]), "+f"(c[3])
                 : "r"(a[0]), "r"(a[1]), "r"(a[2]), "r"(a[3]), "r"(b[0]), "r"(b[1]));
}
__device__ __forceinline__ void bf16_split(float v, bf16& h, bf16& l) {
    h = __float2bfloat16(v);
    l = __float2bfloat16(v - __bfloat162float(h));
}

// ---------------- init / weight prep ----------------
__global__ void init_invf_kernel() {
    int j = threadIdx.x;
    if (j < HDdim / 2) g_invf[j] = (float)exp(-((double)j / 64.0) * log(10000.0));
}
__global__ void rope_table_kernel(const int* __restrict__ pos_ids) {
    int idx = blockIdx.x * 256 + threadIdx.x;         // Mdim*64 entries
    int m = idx >> 6, j = idx & 63;
    float ang = (float)pos_ids[m] * g_invf[j];
    g_rcos[idx] = cosf(ang);
    g_rsin[idx] = sinf(ang);
}
__global__ void pack_convw_split_kernel(const float* __restrict__ conv_w) {
    int inner = blockIdx.x * 256 + threadIdx.x;
    int o = blockIdx.y;
    if (inner >= KCONV * Hdim) return;
    int k = inner >> 11, i = inner & (Hdim - 1);
    float v = conv_w[((size_t)o * Hdim + i) * KCONV + k];
    bf16 h, l; bf16_split(v, h, l);
    size_t oi = (size_t)o * (KCONV * Hdim) + inner;
    g_wcTh[oi] = h; g_wcTl[oi] = l;
}
__global__ void transpose_split_kernel(const float* __restrict__ in, bf16* __restrict__ oh,
                                       bf16* __restrict__ ol, int R, int C) {
    __shared__ float tile[32][33];
    int c0 = blockIdx.x * 32, r0 = blockIdx.y * 32;
    int x = threadIdx.x, y = threadIdx.y;
    #pragma unroll
    for (int j = 0; j < 32; j += 8) tile[y + j][x] = in[(size_t)(r0 + y + j) * C + c0 + x];
    __syncthreads();
    #pragma unroll
    for (int j = 0; j < 32; j += 8) {
        bf16 h, l; bf16_split(tile[x][y + j], h, l);
        size_t oi = (size_t)(c0 + y + j) * R + r0 + x;
        oh[oi] = h; ol[oi] = l;
    }
}

// ---------------- rmsnorm + split ----------------
__global__ void rmsnorm_split_kernel(const float* __restrict__ x, const float* __restrict__ w,
                                     bf16* __restrict__ yh, bf16* __restrict__ yl) {
    int m = blockIdx.x, t = threadIdx.x;
    const float4* xr = reinterpret_cast<const float4*>(x + (size_t)m * Hdim);
    const float4* wr = reinterpret_cast<const float4*>(w);
    float4 v0 = xr[t], v1 = xr[t + 256];
    float ss = v0.x*v0.x + v0.y*v0.y + v0.z*v0.z + v0.w*v0.w
             + v1.x*v1.x + v1.y*v1.y + v1.z*v1.z + v1.w*v1.w;
    __shared__ float red[8];
    #pragma unroll
    for (int o = 16; o; o >>= 1) ss += __shfl_down_sync(0xffffffffu, ss, o);
    if ((t & 31) == 0) red[t >> 5] = ss;
    __syncthreads();
    if (t < 32) {
        float s = (t < 8) ? red[t] : 0.f;
        #pragma unroll
        for (int o = 4; o; o >>= 1) s += __shfl_down_sync(0xffffffffu, s, o);
        if (t == 0) red[0] = s;
    }
    __syncthreads();
    float sc = rsqrtf(red[0] * (1.0f / Hdim) + EPSf);
    float4 w0 = wr[t], w1 = wr[t + 256];
    float o[8] = { v0.x*sc*w0.x, v0.y*sc*w0.y, v0.z*sc*w0.z, v0.w*sc*w0.w,
                   v1.x*sc*w1.x, v1.y*sc*w1.y, v1.z*sc*w1.z, v1.w*sc*w1.w };
    size_t base = (size_t)m * Hdim;
    bf16 hh[8], ll[8];
    #pragma unroll
    for (int i = 0; i < 8; i++) bf16_split(o[i], hh[i], ll[i]);
    *reinterpret_cast<uint2*>(yh + base + t*4)       = *reinterpret_cast<uint2*>(&hh[0]);
    *reinterpret_cast<uint2*>(yh + base + (t+256)*4) = *reinterpret_cast<uint2*>(&hh[4]);
    *reinterpret_cast<uint2*>(yl + base + t*4)       = *reinterpret_cast<uint2*>(&ll[0]);
    *reinterpret_cast<uint2*>(yl + base + (t+256)*4) = *reinterpret_cast<uint2*>(&ll[4]);
}

// =====================================================================
// 3x-bf16 mma.sync GEMM: loads split into A/B halves, issued mid-iteration.
// =====================================================================
template<bool CONV>
__device__ __forceinline__ void load_stage_A(uint32_t st, int k0,
    const bf16* __restrict__ Ah, const bf16* __restrict__ Al,
    int Kd, int m_base, int tid) {
    int kidx = 0, irow = 0;
    if (CONV) { kidx = k0 >> 11; irow = k0 & (Hdim - 1); }
    #pragma unroll
    for (int h = 0; h < 2; h++) {
        int idx = tid + h * 256;
        int row = idx >> 2;
        int ch = idx & 3;
        uint32_t so = (uint32_t)(row * (SSTR * 2) + ch * 16);
        if (CONV) {
            int gm = m_base + row, tp = gm & (Tdim - 1);
            int ok = (tp - 2 + kidx) >= 0;
            size_t ao = (size_t)(ok ? gm - 2 + kidx : 0) * Hdim + irow + ch * 8;
            cp16(st + so,         Ah + ao, ok ? 16 : 0);
            cp16(st + ATILE + so, Al + ao, ok ? 16 : 0);
        } else {
            size_t ao = (size_t)(m_base + row) * Kd + k0 + ch * 8;
            cp16(st + so,         Ah + ao, 16);
            cp16(st + ATILE + so, Al + ao, 16);
        }
    }
}
__device__ __forceinline__ void load_stage_B(uint32_t st, int k0,
    const bf16* __restrict__ Bth, const bf16* __restrict__ Btl,
    int Kd, int n_base, int tid) {
    #pragma unroll
    for (int h = 0; h < 2; h++) {
        int idx = tid + h * 256;
        int row = idx >> 2;
        int ch = idx & 3;
        uint32_t so = (uint32_t)(row * (SSTR * 2) + ch * 16);
        size_t bo = (size_t)(n_base + row) * Kd + k0 + ch * 8;
        cp16(st + 2*ATILE + so, Bth + bo, 16);
        cp16(st + 3*ATILE + so, Btl + bo, 16);
    }
}

template<bool CONV, bool BIAS, bool SILU, bool RESID, bool OUTF32, bool OUTSPLIT>
__global__ __launch_bounds__(256)
void bmma_gemm(const bf16* __restrict__ Ah, const bf16* __restrict__ Al,
               const bf16* __restrict__ Bth, const bf16* __restrict__ Btl,
               float* __restrict__ Cf, bf16* __restrict__ Ch, bf16* __restrict__ Cl,
               int N, int Kd, const float* __restrict__ bias, const float* __restrict__ resid) {
    extern __shared__ __align__(16) uint8_t dsm[];
    const int tid = threadIdx.x;
    const int warp = tid >> 5, lane = tid & 31;
    const int g = lane >> 2, tg = lane & 3;
    const int wm = (warp >> 2) * 64;
    const int wn = (warp & 3) * 32;
    const int m_base = blockIdx.y * 128, n_base = blockIdx.x * 128;
    const uint32_t base0 = (uint32_t)__cvta_generic_to_shared(dsm);

    float acc[4][4][4];
    #pragma unroll
    for (int i = 0; i < 4; i++)
        #pragma unroll
        for (int j = 0; j < 4; j++) { acc[i][j][0]=0.f; acc[i][j][1]=0.f; acc[i][j][2]=0.f; acc[i][j][3]=0.f; }

    const uint32_t aRow = (uint32_t)(lane & 15);
    const uint32_t aChB = (uint32_t)((lane >> 4) * 16);
    const uint32_t bRow = (uint32_t)((lane & 7) + (lane >> 4) * 8);
    const uint32_t bChB = (uint32_t)(((lane >> 3) & 1) * 16);

    const int ntk = Kd / GBK;
    load_stage_A<CONV>(base0, 0, Ah, Al, Kd, m_base, tid);
    load_stage_B(base0, 0, Bth, Btl, Kd, n_base, tid);
    asm volatile("cp.async.commit_group;" ::: "memory");

    for (int it = 0; it < ntk; ++it) {
        asm volatile("cp.async.wait_group 0;" ::: "memory");
        __syncthreads();
        const uint32_t stg  = base0 + (uint32_t)(it & 1) * STAGE;
        const uint32_t nstg = base0 + (uint32_t)((it + 1) & 1) * STAGE;
        const bool more = (it + 1 < ntk);

        #pragma unroll
        for (int ks = 0; ks < 2; ks++) {
            const uint32_t kOffB = (uint32_t)(ks * 32);
            uint32_t Bh[4][2], Bl[4][2], Ahf[4][4], Alf[4][4];
            #pragma unroll
            for (int ntp = 0; ntp < 2; ntp++) {
                uint32_t addr = stg + 2*ATILE + (uint32_t)(wn + ntp*16 + bRow) * (SSTR*2) + kOffB + bChB;
                uint32_t tr[4];
                ldsm_x4(tr, addr);
                Bh[ntp*2][0]=tr[0]; Bh[ntp*2][1]=tr[1]; Bh[ntp*2+1][0]=tr[2]; Bh[ntp*2+1][1]=tr[3];
                ldsm_x4(tr, addr + ATILE);
                Bl[ntp*2][0]=tr[0]; Bl[ntp*2][1]=tr[1]; Bl[ntp*2+1][0]=tr[2]; Bl[ntp*2+1][1]=tr[3];
            }
            #pragma unroll
            for (int mt = 0; mt < 4; mt++)
                ldsm_x4(Ahf[mt], stg + (uint32_t)(wm + mt*16 + aRow) * (SSTR*2) + kOffB + aChB);
            // pass 1: Ah x Bl
            #pragma unroll
            for (int mt = 0; mt < 4; mt++)
                #pragma unroll
                for (int nt = 0; nt < 4; nt++)
                    mma_bf(acc[mt][nt], Ahf[mt], Bl[nt]);
            if (ks == 0 && more)
                load_stage_A<CONV>(nstg, (it + 1) * GBK, Ah, Al, Kd, m_base, tid);
            #pragma unroll
            for (int mt = 0; mt < 4; mt++)
                ldsm_x4(Alf[mt], stg + ATILE + (uint32_t)(wm + mt*16 + aRow) * (SSTR*2) + kOffB + aChB);
            // pass 2: Al x Bh
            #pragma unroll
            for (int mt = 0; mt < 4; mt++)
                #pragma unroll
                for (int nt = 0; nt < 4; nt++)
                    mma_bf(acc[mt][nt], Alf[mt], Bh[nt]);
            if (ks == 0 && more) {
                load_stage_B(nstg, (it + 1) * GBK, Bth, Btl, Kd, n_base, tid);
                asm volatile("cp.async.commit_group;" ::: "memory");
            }
            // pass 3: Ah x Bh
            #pragma unroll
            for (int mt = 0; mt < 4; mt++)
                #pragma unroll
                for (int nt = 0; nt < 4; nt++)
                    mma_bf(acc[mt][nt], Ahf[mt], Bh[nt]);
        }
    }

    // epilogue
    #pragma unroll
    for (int mt = 0; mt < 4; mt++) {
        #pragma unroll
        for (int nt = 0; nt < 4; nt++) {
            int col = n_base + wn + nt * 8 + tg * 2;
            #pragma unroll
            for (int half = 0; half < 2; half++) {
                int row = m_base + wm + mt * 16 + g + half * 8;
                float c0 = acc[mt][nt][half * 2 + 0];
                float c1 = acc[mt][nt][half * 2 + 1];
                if (BIAS) { c0 += bias[col]; c1 += bias[col + 1]; }
                if (SILU) {
                    c0 = c0 / (1.0f + __expf(-c0));
                    c1 = c1 / (1.0f + __expf(-c1));
                }
                if (RESID) {
                    float2 r = *reinterpret_cast<const float2*>(resid + (size_t)row * N + col);
                    c0 += r.x; c1 += r.y;
                }
                if (OUTF32) {
                    float2 o; o.x = c0; o.y = c1;
                    *reinterpret_cast<float2*>(Cf + (size_t)row * N + col) = o;
                }
                if (OUTSPLIT) {
                    bf16 h0, l0, h1, l1;
                    bf16_split(c0, h0, l0);
                    bf16_split(c1, h1, l1);
                    __nv_bfloat162 hp; hp.x = h0; hp.y = h1;
                    __nv_bfloat162 lp; lp.x = l0; lp.y = l1;
                    *reinterpret_cast<__nv_bfloat162*>(Ch + (size_t)row * N + col) = hp;
                    *reinterpret_cast<__nv_bfloat162*>(Cl + (size_t)row * N + col) = lp;
                }
            }
        }
    }
}

// ---------------- dt / scans ----------------
__global__ void dt_kernel(const float* __restrict__ w_dt, const float* __restrict__ b_dt,
                          const float* __restrict__ dt_bias) {
    int m = blockIdx.x, nh = threadIdx.x >> 5, lane = threadIdx.x & 31;
    const bf16* hh = g_normh + (size_t)m * Hdim;
    const bf16* hl = g_norml + (size_t)m * Hdim;
    float s = 0.f;
    for (int k = lane; k < Hdim; k += 32)
        s += (__bfloat162float(hh[k]) + __bfloat162float(hl[k])) * w_dt[(size_t)k * NHdim + nh];
    #pragma unroll
    for (int o = 16; o; o >>= 1) s += __shfl_down_sync(0xffffffffu, s, o);
    if (lane == 0) {
        float x = s + b_dt[nh] + dt_bias[nh];
        g_dt[m * NHdim + nh] = fmaxf(x, 0.f) + log1pf(expf(-fabsf(x)));
    }
}
__global__ void p_scan_kernel(const float* __restrict__ A_log) {
    int warp = threadIdx.x >> 5, lane = threadIdx.x & 31;
    int b = warp >> 4, nh = warp & (NHdim - 1);
    float Anh = -expf(A_log[nh]);
    int t0 = lane * (Tdim / 32);
    float prod = 1.f;
    for (int i = 0; i < Tdim / 32; i++)
        prod *= expf(Anh * g_dt[(b * Tdim + t0 + i) * NHdim + nh]);
    float x = prod;
    #pragma unroll
    for (int o = 1; o < 32; o <<= 1) {
        float y = __shfl_up_sync(0xffffffffu, x, o);
        if (lane >= o) x *= y;
    }
    float excl = __shfl_up_sync(0xffffffffu, x, 1);
    if (lane == 0) excl = 1.f;
    float run = excl;
    float* prow = g_p + warp * Tdim;
    for (int i = 0; i < Tdim / 32; i++) {
        int t = t0 + i;
        run *= expf(Anh * g_dt[(b * Tdim + t) * NHdim + nh]);
        prow[t] = run;
    }
}
__global__ void scan_partial_kernel() {
    int blk = blockIdx.x, bnh = blk >> 6, c = blk & (NCHUNK - 1);
    int b = bnh >> 4, nh = bnh & (NHdim - 1), hd = threadIdx.x;
    const float* prow = g_p + bnh * Tdim;
    double s = 0.0;
    int t0 = c * CHUNK;
    for (int i = 0; i < CHUNK; i++) {
        int t = t0 + i, m = b * Tdim + t;
        float beta = g_dt[m * NHdim + nh], pv = prow[t];
        float v = g_qv[(size_t)m * (2*Hdim) + Hdim + nh * HDdim + hd];
        s += (double)((beta * v) / (pv + EPSf));
    }
    g_S[(size_t)blk * HDdim + hd] = s;
}
__global__ void scan_carry_kernel() {
    int bnh = blockIdx.x, hd = threadIdx.x;
    double carry = 0.0;
    for (int c = 0; c < NCHUNK; c++) {
        size_t idx = ((size_t)bnh * NCHUNK + c) * HDdim + hd;
        g_carry[idx] = carry;
        carry += g_S[idx];
    }
}
// one batch per launch; RoPE from precomputed table
__global__ void scan_final_kernel(int b) {
    int blk = blockIdx.x;                     // NHdim*NCHUNK blocks
    int nh = blk >> 6, c = blk & (NCHUNK - 1);
    int bnh = b * NHdim + nh;
    int hd = threadIdx.x;
    const float* prow = g_p + bnh * Tdim;
    double s = g_carry[((size_t)bnh * NCHUNK + c) * HDdim + hd];
    const int j = hd & 63;
    const bool even = (hd & 1) == 0;
    int t0 = c * CHUNK;
    for (int i = 0; i < CHUNK; i++) {
        int t = t0 + i, m = b * Tdim + t;
        float beta = g_dt[m * NHdim + nh], pv = prow[t];
        size_t qvbase = (size_t)m * (2*Hdim) + nh * HDdim + hd;
        float v = g_qv[qvbase + Hdim];
        s += (double)((beta * v) / (pv + EPSf));
        float state = (float)((double)pv * s);
        float qv = g_qv[qvbase];
        float qp = __shfl_xor_sync(0xffffffffu, qv, 1);
        float ca = g_rcos[(size_t)m * 64 + j];
        float sa = g_rsin[(size_t)m * 64 + j];
        float qr = even ? (qv * ca - qp * sa) : (qv * ca + qp * sa);
        float outv = qr * state;
        bf16 h, l; bf16_split(outv, h, l);
        size_t oi = (size_t)m * Hdim + nh * HDdim + hd;
        g_scanh[oi] = h; g_scanl[oi] = l;
    }
}

// ---------------- launch (two-stream fork/join, batched scan_final) ----------------
extern "C" void kernel_launch(void* const* d_in, const int* in_sizes, int n_in,
                              void* d_out, int out_size) {
    const float* hidden  = (const float*)d_in[0];
    const int*   pos_ids = (const int*)  d_in[1];
    const float* conv_w  = (const float*)d_in[2];
    const float* conv_b  = (const float*)d_in[3];
    const float* wq      = (const float*)d_in[4];
    const float* wv      = (const float*)d_in[5];
    const float* w_dt    = (const float*)d_in[6];
    const float* b_dt    = (const float*)d_in[7];
    const float* A_log   = (const float*)d_in[8];
    const float* dt_bias = (const float*)d_in[9];
    const float* wo      = (const float*)d_in[10];
    const float* w1      = (const float*)d_in[11];
    const float* w2      = (const float*)d_in[12];
    const float* norm1_w = (const float*)d_in[13];
    const float* norm2_w = (const float*)d_in[14];
    float* out = (float*)d_out;

    bf16 *wcTh,*wcTl,*wqvTh,*wqvTl,*woTh,*woTl,*w1Th,*w1Tl,*w2Th,*w2Tl;
    bf16 *normh,*norml,*xh,*xl,*scanh,*scanl,*interh,*interl;
    float *pqv,*ph2;
    cudaGetSymbolAddress((void**)&wcTh, g_wcTh);     cudaGetSymbolAddress((void**)&wcTl, g_wcTl);
    cudaGetSymbolAddress((void**)&wqvTh, g_wqvTh);   cudaGetSymbolAddress((void**)&wqvTl, g_wqvTl);
    cudaGetSymbolAddress((void**)&woTh, g_woTh);     cudaGetSymbolAddress((void**)&woTl, g_woTl);
    cudaGetSymbolAddress((void**)&w1Th, g_w1Th);     cudaGetSymbolAddress((void**)&w1Tl, g_w1Tl);
    cudaGetSymbolAddress((void**)&w2Th, g_w2Th);     cudaGetSymbolAddress((void**)&w2Tl, g_w2Tl);
    cudaGetSymbolAddress((void**)&normh, g_normh);   cudaGetSymbolAddress((void**)&norml, g_norml);
    cudaGetSymbolAddress((void**)&xh, g_xh);         cudaGetSymbolAddress((void**)&xl, g_xl);
    cudaGetSymbolAddress((void**)&scanh, g_scanh);   cudaGetSymbolAddress((void**)&scanl, g_scanl);
    cudaGetSymbolAddress((void**)&interh, g_interh); cudaGetSymbolAddress((void**)&interl, g_interl);
    cudaGetSymbolAddress((void**)&pqv, g_qv);
    cudaGetSymbolAddress((void**)&ph2, g_h2);

    cudaFuncSetAttribute(bmma_gemm<true,true,false,false,false,true>,   cudaFuncAttributeMaxDynamicSharedMemorySize, DYN_SMEM);
    cudaFuncSetAttribute(bmma_gemm<false,false,false,false,true,false>, cudaFuncAttributeMaxDynamicSharedMemorySize, DYN_SMEM);
    cudaFuncSetAttribute(bmma_gemm<false,false,false,true,true,false>,  cudaFuncAttributeMaxDynamicSharedMemorySize, DYN_SMEM);
    cudaFuncSetAttribute(bmma_gemm<false,false,true,false,false,true>,  cudaFuncAttributeMaxDynamicSharedMemorySize, DYN_SMEM);

    cudaStream_t sB;
    cudaStreamCreateWithFlags(&sB, cudaStreamNonBlocking);
    cudaEvent_t eFork, ePack, eNorm, eV, eQ0, eSF0;
    cudaEventCreateWithFlags(&eFork, cudaEventDisableTiming);
    cudaEventCreateWithFlags(&ePack, cudaEventDisableTiming);
    cudaEventCreateWithFlags(&eNorm, cudaEventDisableTiming);
    cudaEventCreateWithFlags(&eV,    cudaEventDisableTiming);
    cudaEventCreateWithFlags(&eQ0,   cudaEventDisableTiming);
    cudaEventCreateWithFlags(&eSF0,  cudaEventDisableTiming);
    cudaEvent_t eScan;
    cudaEventCreateWithFlags(&eScan, cudaEventDisableTiming);

    cudaEventRecord(eFork, 0);
    cudaStreamWaitEvent(sB, eFork, 0);

    // ---- side: conv pack, rope table, weight transposes ----
    pack_convw_split_kernel<<<dim3(24, Hdim), 256, 0, sB>>>(conv_w);
    cudaEventRecord(ePack, sB);
    init_invf_kernel<<<1, 64, 0, sB>>>();
    rope_table_kernel<<<Mdim * 64 / 256, 256, 0, sB>>>(pos_ids);
    transpose_split_kernel<<<dim3(Hdim/32, Hdim/32), dim3(32,8), 0, sB>>>(wq, wqvTh, wqvTl, Hdim, Hdim);
    transpose_split_kernel<<<dim3(Hdim/32, Hdim/32), dim3(32,8), 0, sB>>>(
        wv, wqvTh + (size_t)Hdim*Hdim, wqvTl + (size_t)Hdim*Hdim, Hdim, Hdim);
    transpose_split_kernel<<<dim3(Hdim/32, Hdim/32), dim3(32,8), 0, sB>>>(wo, woTh, woTl, Hdim, Hdim);
    transpose_split_kernel<<<dim3(INTERd/32, Hdim/32), dim3(32,8), 0, sB>>>(w1, w1Th, w1Tl, Hdim, INTERd);
    transpose_split_kernel<<<dim3(Hdim/32, INTERd/32), dim3(32,8), 0, sB>>>(w2, w2Th, w2Tl, INTERd, Hdim);

    // ---- main: rmsnorm1, conv GEMM ----
    rmsnorm_split_kernel<<<Mdim, 256>>>(hidden, norm1_w, normh, norml);
    cudaEventRecord(eNorm, 0);
    cudaStreamWaitEvent(0, ePack, 0);
    bmma_gemm<true,true,false,false,false,true><<<dim3(16,64), 256, DYN_SMEM>>>(
        normh, norml, wcTh, wcTl, nullptr, xh, xl, Hdim, KCONV*Hdim, conv_b, nullptr);

    // ---- side: dt chain ----
    cudaStreamWaitEvent(sB, eNorm, 0);
    dt_kernel<<<Mdim, NHdim*32, 0, sB>>>(w_dt, b_dt, dt_bias);
    p_scan_kernel<<<1, 1024, 0, sB>>>(A_log);

    // ---- main: v GEMM (cols 2048..4095 of g_qv) ----
    bmma_gemm<false,false,false,false,true,false><<<dim3(16,64), 256, DYN_SMEM>>>(
        xh, xl, wqvTh + (size_t)Hdim*Hdim, wqvTl + (size_t)Hdim*Hdim,
        pqv + Hdim, nullptr, nullptr, 2*Hdim, Hdim, nullptr, nullptr);
    cudaEventRecord(eV, 0);

    // ---- side: scan partial+carry under q GEMMs ----
    cudaStreamWaitEvent(sB, eV, 0);
    scan_partial_kernel<<<Bdim*NHdim*NCHUNK, HDdim, 0, sB>>>();
    scan_carry_kernel<<<Bdim*NHdim, HDdim, 0, sB>>>();
    cudaEventRecord(eScan, sB);

    // ---- main: q GEMM batch 0 (rows 0..4095) ----
    bmma_gemm<false,false,false,false,true,false><<<dim3(16,32), 256, DYN_SMEM>>>(
        xh, xl, wqvTh, wqvTl, pqv, nullptr, nullptr, 2*Hdim, Hdim, nullptr, nullptr);
    cudaEventRecord(eQ0, 0);
    // ---- main: q GEMM batch 1 (rows 4096..8191) ----
    bmma_gemm<false,false,false,false,true,false><<<dim3(16,32), 256, DYN_SMEM>>>(
        xh + (size_t)Tdim*Hdim, xl + (size_t)Tdim*Hdim, wqvTh, wqvTl,
        pqv + (size_t)Tdim*2*Hdim, nullptr, nullptr, 2*Hdim, Hdim, nullptr, nullptr);

    // ---- side: scan_final(b=0) under q GEMM batch 1 ----
    cudaStreamWaitEvent(sB, eQ0, 0);
    scan_final_kernel<<<NHdim*NCHUNK, HDdim, 0, sB>>>(0);
    cudaEventRecord(eSF0, sB);

    // ---- main: scan_final(b=1) (needs carry) then join ----
    cudaStreamWaitEvent(0, eScan, 0);
    scan_final_kernel<<<NHdim*NCHUNK, HDdim>>>(1);
    cudaStreamWaitEvent(0, eSF0, 0);
    bmma_gemm<false,false,false,true,true,false><<<dim3(16,64), 256, DYN_SMEM>>>(
        scanh, scanl, woTh, woTl, ph2, nullptr, nullptr, Hdim, Hdim, nullptr, hidden);

    // mlp branch
    rmsnorm_split_kernel<<<Mdim, 256>>>(ph2, norm2_w, normh, norml);
    bmma_gemm<false,false,true,false,false,true><<<dim3(64,64), 256, DYN_SMEM>>>(
        normh, norml, w1Th, w1Tl, nullptr, interh, interl, INTERd, Hdim, nullptr, nullptr);
    bmma_gemm<false,false,false,true,true,false><<<dim3(16,64), 256, DYN_SMEM>>>(
        interh, interl, w2Th, w2Tl, out, nullptr, nullptr, Hdim, INTERd, nullptr, ph2);
}